// round 11
// baseline (speedup 1.0000x reference)
#include <cuda_runtime.h>
#include <cuda_bf16.h>
#include <cstdint>
#include <cfloat>

// ---------------------------------------------------------------------------
// SpanModel: cls, span_repr = spanMLP(spanmax,cls,width), top8(entity sims),
// star-GCN (2 layers). sims via bf16 mma.sync filter (bulk-DMA B tiles,
// 1024-thread CTAs, packed-key top-8 with threshold fast-path) + exact fp32
// refine. GCN reassociated: Y=ET@W1 precompute, Z=h@W2 + fused mix.
// ---------------------------------------------------------------------------

#define TPB 256
#define A_PAD 65
#define SMEM_FLOATS (256 * A_PAD + 64 * 128)
#define SMEM_BYTES (SMEM_FLOATS * 4)

enum { M_SPAN = 0, M_PLAIN = 1 };

static const int NE = 50000;
static const int NEP = 50176;        // padded to 392*128
static const int NROWS = 8192;       // Wmax*B*S
static const int NTILES_SEG = 196;   // tiles per entity segment (392/2)

// ------------------------- scratch (device globals) -----------------------
__device__ __align__(16) uint8_t g_ETraw[(size_t)NEP * 512]; // bf16, tile-blocked SW128
__device__ float g_spanmax[8L * 1024 * 256];   // [w][b][s][h]
__device__ float g_rowbias[32 * 256];          // per (w,b) bias row
__device__ int   g_cand[2L * 8192 * 16];       // candidate indices per eseg
__device__ int   g_topk[8192L * 8];            // final sorted top-8 indices
__device__ float g_ybuf[(size_t)NEP * 256];    // Y = ET @ W1
__device__ float g_hbuf[65536L * 256];         // relu hidden
__device__ float g_zbuf[65536L * 256];         // Z = h @ W2

// ------------------------- PTX helpers -------------------------------------
__device__ __forceinline__ uint32_t smem_u32(const void* p) {
    uint32_t a;
    asm("{ .reg .u64 t; cvta.to.shared.u64 t, %1; cvt.u32.u64 %0, t; }"
        : "=r"(a) : "l"(p));
    return a;
}

#define STS32(addr, v) \
    asm volatile("st.shared.b32 [%0], %1;" :: "r"(addr), "r"(v) : "memory")

#define MBAR_INIT(addr, cnt) \
    asm volatile("mbarrier.init.shared.b64 [%0], %1;" :: "r"(addr), "r"(cnt) : "memory")
#define MBAR_ARRIVE(addr) \
    asm volatile("mbarrier.arrive.shared.b64 _, [%0];" :: "r"(addr) : "memory")
#define MBAR_EXPECT_TX(addr, bytes) \
    asm volatile("mbarrier.arrive.expect_tx.shared.b64 _, [%0], %1;" \
                 :: "r"(addr), "r"(bytes) : "memory")
#define BULK_LD(dst, src, bytes, mbar) \
    asm volatile("cp.async.bulk.shared::cta.global.mbarrier::complete_tx::bytes " \
                 "[%0], [%1], %2, [%3];" \
                 :: "r"(dst), "l"(src), "r"(bytes), "r"(mbar) : "memory")

__device__ __forceinline__ void waitp(uint32_t mbar, uint32_t phase) {
    asm volatile(
        "{\n\t.reg .pred P;\n\t"
        "WL%=:\n\t"
        "mbarrier.try_wait.parity.acquire.cta.shared::cta.b64 P, [%0], %1, 0x989680;\n\t"
        "@P bra WD%=;\n\t"
        "bra WL%=;\n\t"
        "WD%=:\n\t}"
        :: "r"(mbar), "r"(phase) : "memory");
}

#define LDMX4(r0, r1, r2, r3, addr) \
    asm volatile("ldmatrix.sync.aligned.m8n8.x4.shared.b16 {%0,%1,%2,%3}, [%4];" \
                 : "=r"(r0), "=r"(r1), "=r"(r2), "=r"(r3) : "r"(addr))

#define MMA16816(c, a0, a1, a2, a3, b0, b1) \
    asm volatile("mma.sync.aligned.m16n8k16.row.col.f32.bf16.bf16.f32 " \
                 "{%0,%1,%2,%3}, {%4,%5,%6,%7}, {%8,%9}, {%0,%1,%2,%3};" \
                 : "+f"((c)[0]), "+f"((c)[1]), "+f"((c)[2]), "+f"((c)[3]) \
                 : "r"(a0), "r"(a1), "r"(a2), "r"(a3), "r"(b0), "r"(b1))

// blocked SW128 layout for a 128-row x 512-byte bf16 tile (64 atoms x 1KB)
__device__ __forceinline__ uint32_t tileoff(int r, int cb) {
    int b = ((r >> 3) + (cb >> 7) * 16) * 1024 + (r & 7) * 128 + (cb & 127);
    return (uint32_t)(b ^ ((b >> 3) & 0x70));
}

// ------------------------- top-k helpers -----------------------------------
__device__ __forceinline__ bool better(float v1, int i1, float v2, int i2) {
    return (v1 > v2) || (v1 == v2 && i1 < i2);
}

__device__ __forceinline__ void insert8(float tv[8], int ti[8], float v, int e) {
    if (better(v, e, tv[7], ti[7])) {
        tv[7] = v; ti[7] = e;
#pragma unroll
        for (int j = 7; j > 0; --j) {
            if (better(tv[j], ti[j], tv[j - 1], ti[j - 1])) {
                float fv = tv[j]; tv[j] = tv[j - 1]; tv[j - 1] = fv;
                int ii = ti[j]; ti[j] = ti[j - 1]; ti[j - 1] = ii;
            }
        }
    }
}

// order-preserving float->uint transform, upper 17 bits kept
__device__ __forceinline__ uint32_t keyupper(float v) {
    uint32_t u = __float_as_uint(v);
    u ^= (uint32_t)((int32_t)u >> 31) | 0x80000000u;
    return u & 0xFFFF8000u;
}
// packed sortable key: [31:15] value bits, [14:0] 0x7FFF-eloc
__device__ __forceinline__ uint32_t sortkey(float v, int eloc) {
    return keyupper(v) | (uint32_t)(0x7FFF - eloc);
}

__device__ __forceinline__ void insert8u(uint32_t k[8], uint32_t key) {
    if (key > k[7]) {
        k[7] = key;
#pragma unroll
        for (int j = 7; j > 0; --j) {
            if (k[j] > k[j - 1]) { uint32_t t = k[j]; k[j] = k[j - 1]; k[j - 1] = t; }
        }
    }
}

__device__ __noinline__ void insert16u_slow(uint32_t* tk, uint32_t key) {
    int q = 15;
    while (q > 0 && key > tk[q - 1]) { tk[q] = tk[q - 1]; --q; }
    tk[q] = key;
}

// ------------------------- fused prep kernel -------------------------------
__global__ void k_prep(const float* __restrict__ emb, const float* __restrict__ ET,
                       const float* __restrict__ spanW, const float* __restrict__ spanb,
                       float* __restrict__ out_cls) {
    int blk = blockIdx.x;
    if (blk < 6272) {
        int g = blk * 256 + threadIdx.x;   // one 16B output chunk
        int r = g >> 5, ch = g & 31;
        uint4 o = make_uint4(0u, 0u, 0u, 0u);
        if (r < NE) {
            const float4* s = (const float4*)&ET[(size_t)r * 256 + ch * 8];
            float4 v0 = s[0], v1 = s[1];
            __nv_bfloat162 p0 = {__float2bfloat16(v0.x), __float2bfloat16(v0.y)};
            __nv_bfloat162 p1 = {__float2bfloat16(v0.z), __float2bfloat16(v0.w)};
            __nv_bfloat162 p2 = {__float2bfloat16(v1.x), __float2bfloat16(v1.y)};
            __nv_bfloat162 p3 = {__float2bfloat16(v1.z), __float2bfloat16(v1.w)};
            o = make_uint4(*(uint32_t*)&p0, *(uint32_t*)&p1,
                           *(uint32_t*)&p2, *(uint32_t*)&p3);
        }
        size_t tile = (size_t)(r >> 7);
        *(uint4*)(g_ETraw + tile * 65536 + tileoff(r & 127, ch * 16)) = o;
    } else if (blk < 7296) {
        int g = (blk - 6272) * 256 + threadIdx.x;   // b*65536 + s*256 + h
        int h = g & 255, s = (g >> 8) & 255, b = g >> 16;
        float v0 = emb[g];
        float cur = v0;
        g_spanmax[g] = cur;
#pragma unroll
        for (int w = 1; w < 8; ++w) {
            if (s + w < 256) cur = fmaxf(cur, emb[((size_t)b * 256 + s + w) * 256 + h]);
            g_spanmax[(size_t)w * 262144 + g] = cur;
        }
        if (s == 0) out_cls[b * 256 + h] = v0;
    } else {
        int bw = blk - 7296;
        int w = bw >> 2, b = bw & 3;
        int h = threadIdx.x;
        __shared__ float cls_s[256];
        cls_s[h] = emb[(size_t)b * 65536 + h];
        __syncthreads();
        float acc = spanb[h] + (float)(w + 1) * spanW[512 * 256 + h];
        for (int j = 0; j < 256; ++j)
            acc = fmaf(cls_s[j], spanW[(256 + j) * 256 + h], acc);
        g_rowbias[bw * 256 + h] = acc;
    }
}

// ------------------------- FFMA GEMM ----------------------------------------

__device__ __forceinline__ void fill_a(float* a_sm, const float* __restrict__ A,
                                       int row0, int tid, int rowmax) {
#pragma unroll
    for (int it = 0; it < 16; ++it) {
        int f = tid + 256 * it;
        int r = f >> 6;
        int q = f & 63;
        int rr = min(row0 + r, rowmax);
        float4 v = *(const float4*)&A[(size_t)rr * 256 + 4 * q];
        a_sm[(4 * q + 0) * A_PAD + r] = v.x;
        a_sm[(4 * q + 1) * A_PAD + r] = v.y;
        a_sm[(4 * q + 2) * A_PAD + r] = v.z;
        a_sm[(4 * q + 3) * A_PAD + r] = v.w;
    }
}

__device__ __forceinline__ void fill_b(float* b_sm, const float* __restrict__ Bg,
                                       int ldb, int colBase, int kc, int tid) {
#pragma unroll
    for (int it = 0; it < 8; ++it) {
        int f = tid + 256 * it;
        int kk = f >> 5;
        int e4 = f & 31;
        int gc = colBase + 4 * e4;
        float4 v = *(const float4*)&Bg[((size_t)(kc * 64 + kk)) * ldb + gc];
        int cx = ((kk >> 3) & 7) << 2;
        *(float4*)&b_sm[kk * 128 + ((4 * e4) ^ cx)] = v;
    }
}

__device__ __forceinline__ void compute_chunk(const float* __restrict__ a_sm,
                                              const float* __restrict__ b_sm,
                                              float acc[4][8], int kc, int rb, int tc) {
    const int cA = tc * 4;
    const int cB = 64 + tc * 4;
#pragma unroll 8
    for (int kk = 0; kk < 64; ++kk) {
        int kg = kc * 64 + kk;
        float a0 = a_sm[kg * A_PAD + rb + 0];
        float a1 = a_sm[kg * A_PAD + rb + 1];
        float a2 = a_sm[kg * A_PAD + rb + 2];
        float a3 = a_sm[kg * A_PAD + rb + 3];
        int cx = ((kk >> 3) & 7) << 2;
        const float4 b0 = *(const float4*)&b_sm[kk * 128 + (cA ^ cx)];
        const float4 b1 = *(const float4*)&b_sm[kk * 128 + (cB ^ cx)];
        float bj[8] = {b0.x, b0.y, b0.z, b0.w, b1.x, b1.y, b1.z, b1.w};
        float ai[4] = {a0, a1, a2, a3};
#pragma unroll
        for (int i = 0; i < 4; ++i)
#pragma unroll
            for (int j = 0; j < 8; ++j)
                acc[i][j] = fmaf(ai[i], bj[j], acc[i][j]);
    }
}

template <int MODE>
__global__ void __launch_bounds__(256, 2)
gemm_k(const float* __restrict__ A, const float* __restrict__ Bg, int ldb,
       const float* __restrict__ bias, float* __restrict__ C, int rowmax) {
    extern __shared__ float sm[];
    float* a_sm = sm;
    float* b_sm = sm + 256 * A_PAD;
    int tid = threadIdx.x;

    int mt = blockIdx.x >> 1, nt = blockIdx.x & 1;
    int row0 = mt * 64;
    fill_a(a_sm, A, row0, tid, rowmax);
    __syncthreads();

    int trow = tid >> 4, tc = tid & 15;
    int rb = trow * 4;

    float acc[4][8];
#pragma unroll
    for (int i = 0; i < 4; ++i)
#pragma unroll
        for (int j = 0; j < 8; ++j) acc[i][j] = 0.f;

#pragma unroll 1
    for (int kc = 0; kc < 4; ++kc) {
        if (kc) __syncthreads();
        fill_b(b_sm, Bg, ldb, nt * 128, kc, tid);
        __syncthreads();
        compute_chunk(a_sm, b_sm, acc, kc, rb, tc);
    }

    int c0 = nt * 128 + tc * 4;
    int c1 = c0 + 64;
    if (MODE == M_PLAIN) {
#pragma unroll
        for (int i = 0; i < 4; ++i) {
            size_t ro = (size_t)(row0 + rb + i) * 256;
            *(float4*)&C[ro + c0] =
                make_float4(acc[i][0], acc[i][1], acc[i][2], acc[i][3]);
            *(float4*)&C[ro + c1] =
                make_float4(acc[i][4], acc[i][5], acc[i][6], acc[i][7]);
        }
    } else { // M_SPAN: per-(w,b) row bias
#pragma unroll
        for (int i = 0; i < 4; ++i) {
            int row = row0 + rb + i;
            const float* rbp = bias + ((row >> 8) * 256);
            size_t ro = (size_t)row * 256;
            float o[8];
#pragma unroll
            for (int j = 0; j < 4; ++j) {
                o[j] = acc[i][j] + rbp[c0 + j];
                o[4 + j] = acc[i][4 + j] + rbp[c1 + j];
            }
            *(float4*)&C[ro + c0] = make_float4(o[0], o[1], o[2], o[3]);
            *(float4*)&C[ro + c1] = make_float4(o[4], o[5], o[6], o[7]);
        }
    }
}

// ------------------------- bf16 mma sims + top-k filter --------------------
// grid (64 row-tiles, 2 esegs), 1024 threads (32 warps, 48% occ).
// smem: A bf16 128x256 (64KB) @0, B stages 2x64KB @64KB (bulk-DMA'd), bars @192KB.
// warp w: rows (w>>2)*16..+15, cols (w&3)*32..+31 of each 128x128 tile.

#define MK_SMEM (1024 + 196608 + 128)

__global__ void __launch_bounds__(1024, 1)
mma_topk(const float* __restrict__ spanrepr) {
    extern __shared__ char rawsm[];
    char* smb = (char*)(((uintptr_t)rawsm + 1023) & ~(uintptr_t)1023);
    uint32_t sbase = smem_u32(smb);
    const uint32_t BARS = sbase + 196608;
    int tid = threadIdx.x;
    int w = tid >> 5, lane = tid & 31;

    int row0 = blockIdx.x * 128;
    int ebase = blockIdx.y * (NTILES_SEG * 128);
    int tbase = blockIdx.y * NTILES_SEG;

    if (tid == 0) {
        MBAR_INIT(BARS + 0, 1);  MBAR_INIT(BARS + 8, 1);    // full (tx-based)
        MBAR_INIT(BARS + 16, 32); MBAR_INIT(BARS + 24, 32); // empty (32 warps)
    }

    // A tile: span_repr rows -> bf16 blocked SW128 layout
    for (int i = tid; i < 128 * 128; i += 1024) {
        int r = i >> 7, c = (i & 127) * 2;
        float2 v = *(const float2*)&spanrepr[(size_t)(row0 + r) * 256 + c];
        __nv_bfloat162 bb = {__float2bfloat16(v.x), __float2bfloat16(v.y)};
        STS32(sbase + tileoff(r, c * 2), *(uint32_t*)&bb);
    }
    __syncthreads();

    // prefetch tile 0
    if (tid == 0) {
        MBAR_EXPECT_TX(BARS + 0, 65536u);
        BULK_LD(sbase + 65536, (const void*)(g_ETraw + (size_t)tbase * 65536),
                65536u, BARS + 0);
    }

    const int wr = (w >> 2) * 16;
    const int wc = (w & 3) * 32;

    uint32_t k1[8], k2[8];
#pragma unroll
    for (int j = 0; j < 8; ++j) { k1[j] = 0u; k2[j] = 0u; }

    const int a_r = wr + ((lane >> 3) & 1) * 8 + (lane & 7);
    const int a_cb = ((lane >> 4) & 1) * 16;
    const int b_rbase = wc + ((lane >> 4) & 1) * 8 + (lane & 7);
    const int b_cb = ((lane >> 3) & 1) * 16;

#pragma unroll 1
    for (int i = 0; i < NTILES_SEG; ++i) {
        int s = i & 1, n = i >> 1;
        if (tid == 0 && i + 1 < NTILES_SEG) {
            int j = i + 1, s2 = j & 1;
            if (j >= 2) waitp(BARS + 16 + s2 * 8, ((j >> 1) + 1) & 1);
            MBAR_EXPECT_TX(BARS + 0 + s2 * 8, 65536u);
            BULK_LD(sbase + 65536 + s2 * 65536,
                    (const void*)(g_ETraw + (size_t)(tbase + j) * 65536),
                    65536u, BARS + 0 + s2 * 8);
        }
        waitp(BARS + 0 + s * 8, n & 1);

        uint32_t bufb = sbase + 65536 + s * 65536;
        float acc[4][4];
#pragma unroll
        for (int q = 0; q < 4; ++q)
#pragma unroll
            for (int j = 0; j < 4; ++j) acc[q][j] = 0.f;

#pragma unroll 4
        for (int ks = 0; ks < 16; ++ks) {
            uint32_t a0, a1, a2, a3;
            LDMX4(a0, a1, a2, a3, sbase + tileoff(a_r, ks * 32 + a_cb));
#pragma unroll
            for (int p = 0; p < 2; ++p) {
                uint32_t b0, b1, b2, b3;
                LDMX4(b0, b1, b2, b3,
                      bufb + tileoff(b_rbase + p * 16, ks * 32 + b_cb));
                MMA16816(acc[2 * p], a0, a1, a2, a3, b0, b1);
                MMA16816(acc[2 * p + 1], a0, a1, a2, a3, b2, b3);
            }
        }
        __syncwarp();
        if (lane == 0) MBAR_ARRIVE(BARS + 16 + s * 8);  // acc in regs -> stage free

        // fold: threshold fast-path, then packed-key top-8 per stream
        int ebloc = i * 128 + wc + (lane & 3) * 2;
        float m1 = fmaxf(fmaxf(fmaxf(acc[0][0], acc[0][1]),
                               fmaxf(acc[1][0], acc[1][1])),
                         fmaxf(fmaxf(acc[2][0], acc[2][1]),
                               fmaxf(acc[3][0], acc[3][1])));
        if ((keyupper(m1) | 0x7FFFu) > k1[7]) {
#pragma unroll
            for (int q = 0; q < 4; ++q) {
                int el = ebloc + q * 8;
                insert8u(k1, sortkey(acc[q][0], el));
                insert8u(k1, sortkey(acc[q][1], el + 1));
            }
        }
        float m2 = fmaxf(fmaxf(fmaxf(acc[0][2], acc[0][3]),
                               fmaxf(acc[1][2], acc[1][3])),
                         fmaxf(fmaxf(acc[2][2], acc[2][3]),
                               fmaxf(acc[3][2], acc[3][3])));
        if ((keyupper(m2) | 0x7FFFu) > k2[7]) {
#pragma unroll
            for (int q = 0; q < 4; ++q) {
                int el = ebloc + q * 8;
                insert8u(k2, sortkey(acc[q][2], el));
                insert8u(k2, sortkey(acc[q][3], el + 1));
            }
        }
    }

    // -------- CTA merge: 16 streams/row -> top-16/row --------
    __syncthreads();
    uint32_t* mk = (uint32_t*)(smb + 65536);      // [128][128] keys (64KB)
    int sid = (w & 3) * 4 + (lane & 3);
    int r1 = wr + (lane >> 2), r2 = r1 + 8;
#pragma unroll
    for (int j = 0; j < 8; ++j) {
        mk[r1 * 128 + sid * 8 + j] = k1[j];
        mk[r2 * 128 + sid * 8 + j] = k2[j];
    }
    __syncthreads();
    if (tid < 128) {
        uint32_t tk[16];
#pragma unroll
        for (int j = 0; j < 16; ++j) tk[j] = 0u;
        for (int q = 0; q < 128; ++q) {
            uint32_t key = mk[tid * 128 + q];
            if (key > tk[15]) insert16u_slow(tk, key);
        }
        int* cp = &g_cand[((size_t)blockIdx.y * 8192 + row0 + tid) * 16];
#pragma unroll
        for (int j = 0; j < 16; ++j) {
            int e = ebase + (0x7FFF - (int)(tk[j] & 0x7FFFu));
            cp[j] = (e < NE) ? e : 0;   // clamp (padded sims never win anyway)
        }
    }
}

// ------------------------- exact fp32 refine -------------------------------
__global__ void __launch_bounds__(256)
k_refine(const float* __restrict__ spanrepr, const float* __restrict__ ET) {
    int warp = threadIdx.x >> 5, lane = threadIdx.x & 31;
    int row = blockIdx.x * 8 + warp;

    __shared__ float sims[8][32];
    __shared__ int cidx[8][32];

    if (lane < 16) {
        cidx[warp][lane] = g_cand[((size_t)0 * 8192 + row) * 16 + lane];
        cidx[warp][16 + lane] = g_cand[((size_t)1 * 8192 + row) * 16 + lane];
    }
    float4 a0 = *(const float4*)&spanrepr[(size_t)row * 256 + lane * 8];
    float4 a1 = *(const float4*)&spanrepr[(size_t)row * 256 + lane * 8 + 4];
    __syncwarp();

#pragma unroll 1
    for (int c = 0; c < 32; ++c) {
        int idx = cidx[warp][c];
        const float4* ep = (const float4*)&ET[(size_t)idx * 256 + lane * 8];
        float4 e0 = ep[0], e1 = ep[1];
        float d = a0.x * e0.x + a0.y * e0.y + a0.z * e0.z + a0.w * e0.w
                + a1.x * e1.x + a1.y * e1.y + a1.z * e1.z + a1.w * e1.w;
#pragma unroll
        for (int o = 16; o; o >>= 1) d += __shfl_xor_sync(0xFFFFFFFFu, d, o);
        if (lane == 0) sims[warp][c] = d;
    }
    __syncwarp();
    if (lane == 0) {
        float tv[8]; int ti[8];
#pragma unroll
        for (int j = 0; j < 8; ++j) { tv[j] = -FLT_MAX; ti[j] = 0x7FFFFFFF; }
        for (int c = 0; c < 32; ++c) insert8(tv, ti, sims[warp][c], cidx[warp][c]);
#pragma unroll
        for (int j = 0; j < 8; ++j) g_topk[(size_t)row * 8 + j] = ti[j];
    }
}

// ------------------------- GCN fused stages ---------------------------------
__global__ void k_gather_mix(const float* __restrict__ b1) {
    int n = blockIdx.x, h = threadIdx.x;
    __shared__ int id[8];
    if (h < 8) id[h] = g_topk[n * 8 + h];
    __syncthreads();
    float bb = b1[h];
    float y0 = g_ybuf[(size_t)id[0] * 256 + h];
    float s = 0.f;
    float* outb = g_hbuf + (size_t)n * 8 * 256 + h;
#pragma unroll
    for (int j = 1; j < 8; ++j) {
        float yj = g_ybuf[(size_t)id[j] * 256 + h];
        s += yj;
        outb[j * 256] = fmaxf(0.25f * y0 + 0.5f * yj + bb, 0.f);
    }
    outb[0] = fmaxf(0.125f * y0 + 0.25f * s + bb, 0.f);
}

__global__ void k_mix_out(const float* __restrict__ b2, float* __restrict__ out_sub) {
    int n = blockIdx.x, h = threadIdx.x;
    const float* inb = g_zbuf + (size_t)n * 8 * 256 + h;
    float* outb = out_sub + (size_t)n * 8 * 256 + h;
    float bb = b2[h];
    float z0 = inb[0];
    float s = 0.f;
#pragma unroll
    for (int j = 1; j < 8; ++j) {
        float zj = inb[j * 256];
        s += zj;
        outb[j * 256] = 0.25f * z0 + 0.5f * zj + bb;
    }
    outb[0] = 0.125f * z0 + 0.25f * s + bb;
}

// ------------------------- host --------------------------------------------
extern "C" void kernel_launch(void* const* d_in, const int* in_sizes, int n_in,
                              void* d_out, int out_size) {
    const float* emb = (const float*)d_in[0];
    const float* ET = (const float*)d_in[1];
    const float* spanW = (const float*)d_in[2];
    const float* spanb = (const float*)d_in[3];
    const float* W1 = (const float*)d_in[4];
    const float* b1 = (const float*)d_in[5];
    const float* W2 = (const float*)d_in[6];
    const float* b2 = (const float*)d_in[7];

    float* out = (float*)d_out;
    float* out_cls = out;                       // 4*256
    float* out_spanrepr = out + 1024;           // 8192*256
    float* out_sub = out + 1024 + 8192 * 256;   // 65536*256

    float *spanmax, *rowbias, *ybuf, *hbuf, *zbuf;
    cudaGetSymbolAddress((void**)&spanmax, g_spanmax);
    cudaGetSymbolAddress((void**)&rowbias, g_rowbias);
    cudaGetSymbolAddress((void**)&ybuf, g_ybuf);
    cudaGetSymbolAddress((void**)&hbuf, g_hbuf);
    cudaGetSymbolAddress((void**)&zbuf, g_zbuf);

    cudaFuncSetAttribute(gemm_k<M_SPAN>, cudaFuncAttributeMaxDynamicSharedMemorySize, SMEM_BYTES);
    cudaFuncSetAttribute(gemm_k<M_PLAIN>, cudaFuncAttributeMaxDynamicSharedMemorySize, SMEM_BYTES);
    cudaFuncSetAttribute(mma_topk, cudaFuncAttributeMaxDynamicSharedMemorySize, MK_SMEM);

    // 1) fused prep: entity bf16 pack + cls/spanmax + rowbias
    k_prep<<<7328, TPB>>>(emb, ET, spanW, spanb, out_cls);
    // 2) span_repr = spanmax @ W[0:256] + rowbias
    gemm_k<M_SPAN><<<256, TPB, SMEM_BYTES>>>(spanmax, spanW, 256, rowbias,
                                             out_spanrepr, NROWS - 1);
    // 3) Y = ET @ W1 (independent of top-k)
    gemm_k<M_PLAIN><<<1568, TPB, SMEM_BYTES>>>(ET, W1, 256, nullptr, ybuf, NE - 1);
    // 4) bf16 mma sims + per-eseg top-16 candidate filter (1024 thr, 48% occ)
    mma_topk<<<dim3(64, 2), 1024, MK_SMEM>>>(out_spanrepr);
    // 5) exact fp32 refine -> sorted top-8
    k_refine<<<1024, 256>>>(out_spanrepr, ET);
    // 6) h = relu(mix(Y[topk]) + b1)
    k_gather_mix<<<NROWS, TPB>>>(b1);
    // 7) Z = h @ W2
    gemm_k<M_PLAIN><<<2048, TPB, SMEM_BYTES>>>(hbuf, W2, 256, nullptr, zbuf, 65535);
    // 8) out_sub = mix(Z) + b2
    k_mix_out<<<NROWS, TPB>>>(b2, out_sub);

    (void)in_sizes; (void)n_in; (void)out_size;
}

// round 12
// speedup vs baseline: 1.0670x; 1.0670x over previous
#include <cuda_runtime.h>
#include <cuda_bf16.h>
#include <cstdint>
#include <cfloat>

// ---------------------------------------------------------------------------
// SpanModel: cls, span_repr = spanMLP(spanmax,cls,width), top8(entity sims),
// star-GCN (2 layers). sims via bf16 mma.sync filter (bulk-DMA B tiles,
// 1024-thread CTAs, packed-key top-8, strength-reduced LDSM addressing)
// + exact fp32 refine. GCN reassociated: Y=ET@W1, Z=h@W2 + fused mix.
// ---------------------------------------------------------------------------

#define TPB 256
#define A_PAD 65
#define SMEM_FLOATS (256 * A_PAD + 64 * 128)
#define SMEM_BYTES (SMEM_FLOATS * 4)

enum { M_SPAN = 0, M_PLAIN = 1 };

static const int NE = 50000;
static const int NEP = 50176;        // padded to 392*128
static const int NROWS = 8192;       // Wmax*B*S
static const int NTILES_SEG = 196;   // tiles per entity segment (392/2)

// ------------------------- scratch (device globals) -----------------------
__device__ __align__(16) uint8_t g_ETraw[(size_t)NEP * 512]; // bf16, tile-blocked SW128
__device__ float g_spanmax[8L * 1024 * 256];   // [w][b][s][h]
__device__ float g_rowbias[32 * 256];          // per (w,b) bias row
__device__ int   g_cand[2L * 8192 * 16];       // candidate indices per eseg
__device__ int   g_topk[8192L * 8];            // final sorted top-8 indices
__device__ float g_ybuf[(size_t)NEP * 256];    // Y = ET @ W1
__device__ float g_hbuf[65536L * 256];         // relu hidden
__device__ float g_zbuf[65536L * 256];         // Z = h @ W2

// ------------------------- PTX helpers -------------------------------------
__device__ __forceinline__ uint32_t smem_u32(const void* p) {
    uint32_t a;
    asm("{ .reg .u64 t; cvta.to.shared.u64 t, %1; cvt.u32.u64 %0, t; }"
        : "=r"(a) : "l"(p));
    return a;
}

#define STS32(addr, v) \
    asm volatile("st.shared.b32 [%0], %1;" :: "r"(addr), "r"(v) : "memory")

#define MBAR_INIT(addr, cnt) \
    asm volatile("mbarrier.init.shared.b64 [%0], %1;" :: "r"(addr), "r"(cnt) : "memory")
#define MBAR_ARRIVE(addr) \
    asm volatile("mbarrier.arrive.shared.b64 _, [%0];" :: "r"(addr) : "memory")
#define MBAR_EXPECT_TX(addr, bytes) \
    asm volatile("mbarrier.arrive.expect_tx.shared.b64 _, [%0], %1;" \
                 :: "r"(addr), "r"(bytes) : "memory")
#define BULK_LD(dst, src, bytes, mbar) \
    asm volatile("cp.async.bulk.shared::cta.global.mbarrier::complete_tx::bytes " \
                 "[%0], [%1], %2, [%3];" \
                 :: "r"(dst), "l"(src), "r"(bytes), "r"(mbar) : "memory")

__device__ __forceinline__ void waitp(uint32_t mbar, uint32_t phase) {
    asm volatile(
        "{\n\t.reg .pred P;\n\t"
        "WL%=:\n\t"
        "mbarrier.try_wait.parity.acquire.cta.shared::cta.b64 P, [%0], %1, 0x989680;\n\t"
        "@P bra WD%=;\n\t"
        "bra WL%=;\n\t"
        "WD%=:\n\t}"
        :: "r"(mbar), "r"(phase) : "memory");
}

#define LDMX4(r0, r1, r2, r3, addr) \
    asm volatile("ldmatrix.sync.aligned.m8n8.x4.shared.b16 {%0,%1,%2,%3}, [%4];" \
                 : "=r"(r0), "=r"(r1), "=r"(r2), "=r"(r3) : "r"(addr))

#define MMA16816(c, a0, a1, a2, a3, b0, b1) \
    asm volatile("mma.sync.aligned.m16n8k16.row.col.f32.bf16.bf16.f32 " \
                 "{%0,%1,%2,%3}, {%4,%5,%6,%7}, {%8,%9}, {%0,%1,%2,%3};" \
                 : "+f"((c)[0]), "+f"((c)[1]), "+f"((c)[2]), "+f"((c)[3]) \
                 : "r"(a0), "r"(a1), "r"(a2), "r"(a3), "r"(b0), "r"(b1))

// blocked SW128 layout for a 128-row x 512-byte bf16 tile (64 atoms x 1KB)
__device__ __forceinline__ uint32_t tileoff(int r, int cb) {
    int b = ((r >> 3) + (cb >> 7) * 16) * 1024 + (r & 7) * 128 + (cb & 127);
    return (uint32_t)(b ^ ((b >> 3) & 0x70));
}

// ------------------------- top-k helpers -----------------------------------
__device__ __forceinline__ bool better(float v1, int i1, float v2, int i2) {
    return (v1 > v2) || (v1 == v2 && i1 < i2);
}

__device__ __forceinline__ void insert8(float tv[8], int ti[8], float v, int e) {
    if (better(v, e, tv[7], ti[7])) {
        tv[7] = v; ti[7] = e;
#pragma unroll
        for (int j = 7; j > 0; --j) {
            if (better(tv[j], ti[j], tv[j - 1], ti[j - 1])) {
                float fv = tv[j]; tv[j] = tv[j - 1]; tv[j - 1] = fv;
                int ii = ti[j]; ti[j] = ti[j - 1]; ti[j - 1] = ii;
            }
        }
    }
}

// packed sortable key: [31:15] order-preserving float bits, [14:0] 0x7FFF-eloc
__device__ __forceinline__ uint32_t sortkey(float v, int eloc) {
    uint32_t u = __float_as_uint(v);
    u ^= (uint32_t)((int32_t)u >> 31) | 0x80000000u;
    return (u & 0xFFFF8000u) | (uint32_t)(0x7FFF - eloc);
}

__device__ __forceinline__ void insert8u(uint32_t k[8], uint32_t key) {
    if (key > k[7]) {
        k[7] = key;
#pragma unroll
        for (int j = 7; j > 0; --j) {
            if (k[j] > k[j - 1]) { uint32_t t = k[j]; k[j] = k[j - 1]; k[j - 1] = t; }
        }
    }
}

__device__ __noinline__ void insert16u_slow(uint32_t* tk, uint32_t key) {
    int q = 15;
    while (q > 0 && key > tk[q - 1]) { tk[q] = tk[q - 1]; --q; }
    tk[q] = key;
}

// ------------------------- fused prep kernel -------------------------------
__global__ void k_prep(const float* __restrict__ emb, const float* __restrict__ ET,
                       const float* __restrict__ spanW, const float* __restrict__ spanb,
                       float* __restrict__ out_cls) {
    int blk = blockIdx.x;
    if (blk < 6272) {
        int g = blk * 256 + threadIdx.x;   // one 16B output chunk
        int r = g >> 5, ch = g & 31;
        uint4 o = make_uint4(0u, 0u, 0u, 0u);
        if (r < NE) {
            const float4* s = (const float4*)&ET[(size_t)r * 256 + ch * 8];
            float4 v0 = s[0], v1 = s[1];
            __nv_bfloat162 p0 = {__float2bfloat16(v0.x), __float2bfloat16(v0.y)};
            __nv_bfloat162 p1 = {__float2bfloat16(v0.z), __float2bfloat16(v0.w)};
            __nv_bfloat162 p2 = {__float2bfloat16(v1.x), __float2bfloat16(v1.y)};
            __nv_bfloat162 p3 = {__float2bfloat16(v1.z), __float2bfloat16(v1.w)};
            o = make_uint4(*(uint32_t*)&p0, *(uint32_t*)&p1,
                           *(uint32_t*)&p2, *(uint32_t*)&p3);
        }
        size_t tile = (size_t)(r >> 7);
        *(uint4*)(g_ETraw + tile * 65536 + tileoff(r & 127, ch * 16)) = o;
    } else if (blk < 7296) {
        int g = (blk - 6272) * 256 + threadIdx.x;   // b*65536 + s*256 + h
        int h = g & 255, s = (g >> 8) & 255, b = g >> 16;
        float v0 = emb[g];
        float cur = v0;
        g_spanmax[g] = cur;
#pragma unroll
        for (int w = 1; w < 8; ++w) {
            if (s + w < 256) cur = fmaxf(cur, emb[((size_t)b * 256 + s + w) * 256 + h]);
            g_spanmax[(size_t)w * 262144 + g] = cur;
        }
        if (s == 0) out_cls[b * 256 + h] = v0;
    } else {
        int bw = blk - 7296;
        int w = bw >> 2, b = bw & 3;
        int h = threadIdx.x;
        __shared__ float cls_s[256];
        cls_s[h] = emb[(size_t)b * 65536 + h];
        __syncthreads();
        float acc = spanb[h] + (float)(w + 1) * spanW[512 * 256 + h];
        for (int j = 0; j < 256; ++j)
            acc = fmaf(cls_s[j], spanW[(256 + j) * 256 + h], acc);
        g_rowbias[bw * 256 + h] = acc;
    }
}

// ------------------------- FFMA GEMM ----------------------------------------

__device__ __forceinline__ void fill_a(float* a_sm, const float* __restrict__ A,
                                       int row0, int tid, int rowmax) {
#pragma unroll
    for (int it = 0; it < 16; ++it) {
        int f = tid + 256 * it;
        int r = f >> 6;
        int q = f & 63;
        int rr = min(row0 + r, rowmax);
        float4 v = *(const float4*)&A[(size_t)rr * 256 + 4 * q];
        a_sm[(4 * q + 0) * A_PAD + r] = v.x;
        a_sm[(4 * q + 1) * A_PAD + r] = v.y;
        a_sm[(4 * q + 2) * A_PAD + r] = v.z;
        a_sm[(4 * q + 3) * A_PAD + r] = v.w;
    }
}

__device__ __forceinline__ void fill_b(float* b_sm, const float* __restrict__ Bg,
                                       int ldb, int colBase, int kc, int tid) {
#pragma unroll
    for (int it = 0; it < 8; ++it) {
        int f = tid + 256 * it;
        int kk = f >> 5;
        int e4 = f & 31;
        int gc = colBase + 4 * e4;
        float4 v = *(const float4*)&Bg[((size_t)(kc * 64 + kk)) * ldb + gc];
        int cx = ((kk >> 3) & 7) << 2;
        *(float4*)&b_sm[kk * 128 + ((4 * e4) ^ cx)] = v;
    }
}

__device__ __forceinline__ void compute_chunk(const float* __restrict__ a_sm,
                                              const float* __restrict__ b_sm,
                                              float acc[4][8], int kc, int rb, int tc) {
    const int cA = tc * 4;
    const int cB = 64 + tc * 4;
#pragma unroll 8
    for (int kk = 0; kk < 64; ++kk) {
        int kg = kc * 64 + kk;
        float a0 = a_sm[kg * A_PAD + rb + 0];
        float a1 = a_sm[kg * A_PAD + rb + 1];
        float a2 = a_sm[kg * A_PAD + rb + 2];
        float a3 = a_sm[kg * A_PAD + rb + 3];
        int cx = ((kk >> 3) & 7) << 2;
        const float4 b0 = *(const float4*)&b_sm[kk * 128 + (cA ^ cx)];
        const float4 b1 = *(const float4*)&b_sm[kk * 128 + (cB ^ cx)];
        float bj[8] = {b0.x, b0.y, b0.z, b0.w, b1.x, b1.y, b1.z, b1.w};
        float ai[4] = {a0, a1, a2, a3};
#pragma unroll
        for (int i = 0; i < 4; ++i)
#pragma unroll
            for (int j = 0; j < 8; ++j)
                acc[i][j] = fmaf(ai[i], bj[j], acc[i][j]);
    }
}

template <int MODE>
__global__ void __launch_bounds__(256, 2)
gemm_k(const float* __restrict__ A, const float* __restrict__ Bg, int ldb,
       const float* __restrict__ bias, float* __restrict__ C, int rowmax) {
    extern __shared__ float sm[];
    float* a_sm = sm;
    float* b_sm = sm + 256 * A_PAD;
    int tid = threadIdx.x;

    int mt = blockIdx.x >> 1, nt = blockIdx.x & 1;
    int row0 = mt * 64;
    fill_a(a_sm, A, row0, tid, rowmax);
    __syncthreads();

    int trow = tid >> 4, tc = tid & 15;
    int rb = trow * 4;

    float acc[4][8];
#pragma unroll
    for (int i = 0; i < 4; ++i)
#pragma unroll
        for (int j = 0; j < 8; ++j) acc[i][j] = 0.f;

#pragma unroll 1
    for (int kc = 0; kc < 4; ++kc) {
        if (kc) __syncthreads();
        fill_b(b_sm, Bg, ldb, nt * 128, kc, tid);
        __syncthreads();
        compute_chunk(a_sm, b_sm, acc, kc, rb, tc);
    }

    int c0 = nt * 128 + tc * 4;
    int c1 = c0 + 64;
    if (MODE == M_PLAIN) {
#pragma unroll
        for (int i = 0; i < 4; ++i) {
            size_t ro = (size_t)(row0 + rb + i) * 256;
            *(float4*)&C[ro + c0] =
                make_float4(acc[i][0], acc[i][1], acc[i][2], acc[i][3]);
            *(float4*)&C[ro + c1] =
                make_float4(acc[i][4], acc[i][5], acc[i][6], acc[i][7]);
        }
    } else { // M_SPAN: per-(w,b) row bias
#pragma unroll
        for (int i = 0; i < 4; ++i) {
            int row = row0 + rb + i;
            const float* rbp = bias + ((row >> 8) * 256);
            size_t ro = (size_t)row * 256;
            float o[8];
#pragma unroll
            for (int j = 0; j < 4; ++j) {
                o[j] = acc[i][j] + rbp[c0 + j];
                o[4 + j] = acc[i][4 + j] + rbp[c1 + j];
            }
            *(float4*)&C[ro + c0] = make_float4(o[0], o[1], o[2], o[3]);
            *(float4*)&C[ro + c1] = make_float4(o[4], o[5], o[6], o[7]);
        }
    }
}

// ------------------------- bf16 mma sims + top-k filter --------------------
// grid (64 row-tiles, 2 esegs), 1024 threads (32 warps, 48% occ).
// smem: A bf16 128x256 (64KB) @0, B stages 2x64KB @64KB (bulk-DMA'd), bars @192KB.
// warp w: rows (w>>2)*16..+15, cols (w&3)*32..+31 of each 128x128 tile.
// LDSM addresses strength-reduced: addr = base + unroll-const + off[ks&3].

#define MK_SMEM (1024 + 196608 + 128)

__global__ void __launch_bounds__(1024, 1)
mma_topk(const float* __restrict__ spanrepr) {
    extern __shared__ char rawsm[];
    char* smb = (char*)(((uintptr_t)rawsm + 1023) & ~(uintptr_t)1023);
    uint32_t sbase = smem_u32(smb);
    const uint32_t BARS = sbase + 196608;
    int tid = threadIdx.x;
    int w = tid >> 5, lane = tid & 31;

    int row0 = blockIdx.x * 128;
    int ebase = blockIdx.y * (NTILES_SEG * 128);
    int tbase = blockIdx.y * NTILES_SEG;

    if (tid == 0) {
        MBAR_INIT(BARS + 0, 1);  MBAR_INIT(BARS + 8, 1);    // full (tx-based)
        MBAR_INIT(BARS + 16, 32); MBAR_INIT(BARS + 24, 32); // empty (32 warps)
    }

    // A tile: span_repr rows -> bf16 blocked SW128 layout
    for (int i = tid; i < 128 * 128; i += 1024) {
        int r = i >> 7, c = (i & 127) * 2;
        float2 v = *(const float2*)&spanrepr[(size_t)(row0 + r) * 256 + c];
        __nv_bfloat162 bb = {__float2bfloat16(v.x), __float2bfloat16(v.y)};
        STS32(sbase + tileoff(r, c * 2), *(uint32_t*)&bb);
    }
    __syncthreads();

    // prefetch tile 0
    if (tid == 0) {
        MBAR_EXPECT_TX(BARS + 0, 65536u);
        BULK_LD(sbase + 65536, (const void*)(g_ETraw + (size_t)tbase * 65536),
                65536u, BARS + 0);
    }

    const int wr = (w >> 2) * 16;
    const int wc = (w & 3) * 32;

    uint32_t k1[8], k2[8];
#pragma unroll
    for (int j = 0; j < 8; ++j) { k1[j] = 0u; k2[j] = 0u; }

    const int a_r = wr + ((lane >> 3) & 1) * 8 + (lane & 7);
    const int a_cb = ((lane >> 4) & 1) * 16;
    const int b_rbase = wc + ((lane >> 4) & 1) * 8 + (lane & 7);
    const int b_cb = ((lane >> 3) & 1) * 16;

    // strength-reduced LDSM address components
    const uint32_t aBase = sbase + (uint32_t)((a_r >> 3) * 1024 + (a_r & 7) * 128);
    const uint32_t aMask = (uint32_t)((a_r & 7) << 4);
    const uint32_t bBaseRel = (uint32_t)((b_rbase >> 3) * 1024 + (b_rbase & 7) * 128);
    const uint32_t bMask = (uint32_t)((b_rbase & 7) << 4);
    uint32_t aOff[4], bOff[4];
#pragma unroll
    for (int j = 0; j < 4; ++j) {
        aOff[j] = (uint32_t)((j * 32 + a_cb)) ^ aMask;
        bOff[j] = (uint32_t)((j * 32 + b_cb)) ^ bMask;
    }

#pragma unroll 1
    for (int i = 0; i < NTILES_SEG; ++i) {
        int s = i & 1, n = i >> 1;
        if (tid == 0 && i + 1 < NTILES_SEG) {
            int j = i + 1, s2 = j & 1;
            if (j >= 2) waitp(BARS + 16 + s2 * 8, ((j >> 1) + 1) & 1);
            MBAR_EXPECT_TX(BARS + 0 + s2 * 8, 65536u);
            BULK_LD(sbase + 65536 + s2 * 65536,
                    (const void*)(g_ETraw + (size_t)(tbase + j) * 65536),
                    65536u, BARS + 0 + s2 * 8);
        }
        waitp(BARS + 0 + s * 8, n & 1);

        uint32_t bBase = sbase + 65536 + s * 65536 + bBaseRel;
        float acc[4][4];
#pragma unroll
        for (int q = 0; q < 4; ++q)
#pragma unroll
            for (int j = 0; j < 4; ++j) acc[q][j] = 0.f;

#pragma unroll
        for (int ks = 0; ks < 16; ++ks) {
            const uint32_t kc = (uint32_t)((ks >> 2) * 16384);
            uint32_t a0, a1, a2, a3;
            LDMX4(a0, a1, a2, a3, aBase + kc + aOff[ks & 3]);
#pragma unroll
            for (int p = 0; p < 2; ++p) {
                uint32_t b0, b1, b2, b3;
                LDMX4(b0, b1, b2, b3, bBase + (kc + p * 2048) + bOff[ks & 3]);
                MMA16816(acc[2 * p], a0, a1, a2, a3, b0, b1);
                MMA16816(acc[2 * p + 1], a0, a1, a2, a3, b2, b3);
            }
        }
        __syncwarp();
        if (lane == 0) MBAR_ARRIVE(BARS + 16 + s * 8);  // acc in regs -> stage free

        // fold: packed sortable keys, top-8 per (lane,row-stream)
        int ebloc = i * 128 + wc + (lane & 3) * 2;
#pragma unroll
        for (int q = 0; q < 4; ++q) {
            int el = ebloc + q * 8;
            insert8u(k1, sortkey(acc[q][0], el));
            insert8u(k1, sortkey(acc[q][1], el + 1));
            insert8u(k2, sortkey(acc[q][2], el));
            insert8u(k2, sortkey(acc[q][3], el + 1));
        }
    }

    // -------- CTA merge: 16 streams/row -> top-16/row --------
    __syncthreads();
    uint32_t* mk = (uint32_t*)(smb + 65536);      // [128][128] keys (64KB)
    int sid = (w & 3) * 4 + (lane & 3);
    int r1 = wr + (lane >> 2), r2 = r1 + 8;
#pragma unroll
    for (int j = 0; j < 8; ++j) {
        mk[r1 * 128 + sid * 8 + j] = k1[j];
        mk[r2 * 128 + sid * 8 + j] = k2[j];
    }
    __syncthreads();
    if (tid < 128) {
        uint32_t tk[16];
#pragma unroll
        for (int j = 0; j < 16; ++j) tk[j] = 0u;
        for (int q = 0; q < 128; ++q) {
            uint32_t key = mk[tid * 128 + q];
            if (key > tk[15]) insert16u_slow(tk, key);
        }
        int* cp = &g_cand[((size_t)blockIdx.y * 8192 + row0 + tid) * 16];
#pragma unroll
        for (int j = 0; j < 16; ++j) {
            int e = ebase + (0x7FFF - (int)(tk[j] & 0x7FFFu));
            cp[j] = (e < NE) ? e : 0;   // clamp (padded sims never win anyway)
        }
    }
}

// ------------------------- exact fp32 refine -------------------------------
__global__ void __launch_bounds__(256)
k_refine(const float* __restrict__ spanrepr, const float* __restrict__ ET) {
    int warp = threadIdx.x >> 5, lane = threadIdx.x & 31;
    int row = blockIdx.x * 8 + warp;

    __shared__ float sims[8][32];
    __shared__ int cidx[8][32];

    if (lane < 16) {
        cidx[warp][lane] = g_cand[((size_t)0 * 8192 + row) * 16 + lane];
        cidx[warp][16 + lane] = g_cand[((size_t)1 * 8192 + row) * 16 + lane];
    }
    float4 a0 = *(const float4*)&spanrepr[(size_t)row * 256 + lane * 8];
    float4 a1 = *(const float4*)&spanrepr[(size_t)row * 256 + lane * 8 + 4];
    __syncwarp();

#pragma unroll 1
    for (int c = 0; c < 32; ++c) {
        int idx = cidx[warp][c];
        const float4* ep = (const float4*)&ET[(size_t)idx * 256 + lane * 8];
        float4 e0 = ep[0], e1 = ep[1];
        float d = a0.x * e0.x + a0.y * e0.y + a0.z * e0.z + a0.w * e0.w
                + a1.x * e1.x + a1.y * e1.y + a1.z * e1.z + a1.w * e1.w;
#pragma unroll
        for (int o = 16; o; o >>= 1) d += __shfl_xor_sync(0xFFFFFFFFu, d, o);
        if (lane == 0) sims[warp][c] = d;
    }
    __syncwarp();
    if (lane == 0) {
        float tv[8]; int ti[8];
#pragma unroll
        for (int j = 0; j < 8; ++j) { tv[j] = -FLT_MAX; ti[j] = 0x7FFFFFFF; }
        for (int c = 0; c < 32; ++c) insert8(tv, ti, sims[warp][c], cidx[warp][c]);
#pragma unroll
        for (int j = 0; j < 8; ++j) g_topk[(size_t)row * 8 + j] = ti[j];
    }
}

// ------------------------- GCN fused stages ---------------------------------
__global__ void k_gather_mix(const float* __restrict__ b1) {
    int n = blockIdx.x, h = threadIdx.x;
    __shared__ int id[8];
    if (h < 8) id[h] = g_topk[n * 8 + h];
    __syncthreads();
    float bb = b1[h];
    float y0 = g_ybuf[(size_t)id[0] * 256 + h];
    float s = 0.f;
    float* outb = g_hbuf + (size_t)n * 8 * 256 + h;
#pragma unroll
    for (int j = 1; j < 8; ++j) {
        float yj = g_ybuf[(size_t)id[j] * 256 + h];
        s += yj;
        outb[j * 256] = fmaxf(0.25f * y0 + 0.5f * yj + bb, 0.f);
    }
    outb[0] = fmaxf(0.125f * y0 + 0.25f * s + bb, 0.f);
}

__global__ void k_mix_out(const float* __restrict__ b2, float* __restrict__ out_sub) {
    int n = blockIdx.x, h = threadIdx.x;
    const float* inb = g_zbuf + (size_t)n * 8 * 256 + h;
    float* outb = out_sub + (size_t)n * 8 * 256 + h;
    float bb = b2[h];
    float z0 = inb[0];
    float s = 0.f;
#pragma unroll
    for (int j = 1; j < 8; ++j) {
        float zj = inb[j * 256];
        s += zj;
        outb[j * 256] = 0.25f * z0 + 0.5f * zj + bb;
    }
    outb[0] = 0.125f * z0 + 0.25f * s + bb;
}

// ------------------------- host --------------------------------------------
extern "C" void kernel_launch(void* const* d_in, const int* in_sizes, int n_in,
                              void* d_out, int out_size) {
    const float* emb = (const float*)d_in[0];
    const float* ET = (const float*)d_in[1];
    const float* spanW = (const float*)d_in[2];
    const float* spanb = (const float*)d_in[3];
    const float* W1 = (const float*)d_in[4];
    const float* b1 = (const float*)d_in[5];
    const float* W2 = (const float*)d_in[6];
    const float* b2 = (const float*)d_in[7];

    float* out = (float*)d_out;
    float* out_cls = out;                       // 4*256
    float* out_spanrepr = out + 1024;           // 8192*256
    float* out_sub = out + 1024 + 8192 * 256;   // 65536*256

    float *spanmax, *rowbias, *ybuf, *hbuf, *zbuf;
    cudaGetSymbolAddress((void**)&spanmax, g_spanmax);
    cudaGetSymbolAddress((void**)&rowbias, g_rowbias);
    cudaGetSymbolAddress((void**)&ybuf, g_ybuf);
    cudaGetSymbolAddress((void**)&hbuf, g_hbuf);
    cudaGetSymbolAddress((void**)&zbuf, g_zbuf);

    cudaFuncSetAttribute(gemm_k<M_SPAN>, cudaFuncAttributeMaxDynamicSharedMemorySize, SMEM_BYTES);
    cudaFuncSetAttribute(gemm_k<M_PLAIN>, cudaFuncAttributeMaxDynamicSharedMemorySize, SMEM_BYTES);
    cudaFuncSetAttribute(mma_topk, cudaFuncAttributeMaxDynamicSharedMemorySize, MK_SMEM);

    // 1) fused prep: entity bf16 pack + cls/spanmax + rowbias
    k_prep<<<7328, TPB>>>(emb, ET, spanW, spanb, out_cls);
    // 2) span_repr = spanmax @ W[0:256] + rowbias
    gemm_k<M_SPAN><<<256, TPB, SMEM_BYTES>>>(spanmax, spanW, 256, rowbias,
                                             out_spanrepr, NROWS - 1);
    // 3) Y = ET @ W1 (independent of top-k)
    gemm_k<M_PLAIN><<<1568, TPB, SMEM_BYTES>>>(ET, W1, 256, nullptr, ybuf, NE - 1);
    // 4) bf16 mma sims + per-eseg top-16 candidate filter (1024 thr, 48% occ)
    mma_topk<<<dim3(64, 2), 1024, MK_SMEM>>>(out_spanrepr);
    // 5) exact fp32 refine -> sorted top-8
    k_refine<<<1024, 256>>>(out_spanrepr, ET);
    // 6) h = relu(mix(Y[topk]) + b1)
    k_gather_mix<<<NROWS, TPB>>>(b1);
    // 7) Z = h @ W2
    gemm_k<M_PLAIN><<<2048, TPB, SMEM_BYTES>>>(hbuf, W2, 256, nullptr, zbuf, 65535);
    // 8) out_sub = mix(Z) + b2
    k_mix_out<<<NROWS, TPB>>>(b2, out_sub);

    (void)in_sizes; (void)n_in; (void)out_size;
}

// round 13
// speedup vs baseline: 1.2381x; 1.1604x over previous
#include <cuda_runtime.h>
#include <cuda_bf16.h>
#include <cstdint>
#include <cfloat>

// ---------------------------------------------------------------------------
// SpanModel: cls, span_repr = spanMLP(spanmax,cls,width), top8(entity sims),
// star-GCN (2 layers). sims via bf16 mma.sync filter (bulk-DMA B tiles,
// 1024-thread CTAs, packed-key top-8, strength-reduced LDSM addressing)
// + exact fp32 refine. GCN GEMMs (Y=ET@W1, Z=h@W2) via 3-term split-bf16 HMMA.
// ---------------------------------------------------------------------------

#define TPB 256
#define A_PAD 65
#define SMEM_FLOATS (256 * A_PAD + 64 * 128)
#define SMEM_BYTES (SMEM_FLOATS * 4)

static const int NE = 50000;
static const int NEP = 50176;        // padded to 392*128
static const int NROWS = 8192;       // Wmax*B*S
static const int NTILES_SEG = 196;   // tiles per entity segment (392/2)

// ------------------------- scratch (device globals) -----------------------
__device__ __align__(16) uint8_t g_ETraw[(size_t)NEP * 512]; // bf16, tile-blocked SW128
__device__ __align__(16) uint8_t g_Wp[2][4][65536]; // W1/W2 split-bf16 [m][kh*2+nb]
__device__ float g_spanmax[8L * 1024 * 256];   // [w][b][s][h]
__device__ float g_rowbias[32 * 256];          // per (w,b) bias row
__device__ int   g_cand[2L * 8192 * 16];       // candidate indices per eseg
__device__ int   g_topk[8192L * 8];            // final sorted top-8 indices
__device__ float g_ybuf[(size_t)NEP * 256];    // Y = ET @ W1
__device__ float g_hbuf[65536L * 256];         // relu hidden
__device__ float g_zbuf[65536L * 256];         // Z = h @ W2

// ------------------------- PTX helpers -------------------------------------
__device__ __forceinline__ uint32_t smem_u32(const void* p) {
    uint32_t a;
    asm("{ .reg .u64 t; cvta.to.shared.u64 t, %1; cvt.u32.u64 %0, t; }"
        : "=r"(a) : "l"(p));
    return a;
}

#define STS32(addr, v) \
    asm volatile("st.shared.b32 [%0], %1;" :: "r"(addr), "r"(v) : "memory")

#define MBAR_INIT(addr, cnt) \
    asm volatile("mbarrier.init.shared.b64 [%0], %1;" :: "r"(addr), "r"(cnt) : "memory")
#define MBAR_ARRIVE(addr) \
    asm volatile("mbarrier.arrive.shared.b64 _, [%0];" :: "r"(addr) : "memory")
#define MBAR_EXPECT_TX(addr, bytes) \
    asm volatile("mbarrier.arrive.expect_tx.shared.b64 _, [%0], %1;" \
                 :: "r"(addr), "r"(bytes) : "memory")
#define BULK_LD(dst, src, bytes, mbar) \
    asm volatile("cp.async.bulk.shared::cta.global.mbarrier::complete_tx::bytes " \
                 "[%0], [%1], %2, [%3];" \
                 :: "r"(dst), "l"(src), "r"(bytes), "r"(mbar) : "memory")

__device__ __forceinline__ void waitp(uint32_t mbar, uint32_t phase) {
    asm volatile(
        "{\n\t.reg .pred P;\n\t"
        "WL%=:\n\t"
        "mbarrier.try_wait.parity.acquire.cta.shared::cta.b64 P, [%0], %1, 0x989680;\n\t"
        "@P bra WD%=;\n\t"
        "bra WL%=;\n\t"
        "WD%=:\n\t}"
        :: "r"(mbar), "r"(phase) : "memory");
}

#define LDMX4(r0, r1, r2, r3, addr) \
    asm volatile("ldmatrix.sync.aligned.m8n8.x4.shared.b16 {%0,%1,%2,%3}, [%4];" \
                 : "=r"(r0), "=r"(r1), "=r"(r2), "=r"(r3) : "r"(addr))

#define MMA16816(c, a0, a1, a2, a3, b0, b1) \
    asm volatile("mma.sync.aligned.m16n8k16.row.col.f32.bf16.bf16.f32 " \
                 "{%0,%1,%2,%3}, {%4,%5,%6,%7}, {%8,%9}, {%0,%1,%2,%3};" \
                 : "+f"((c)[0]), "+f"((c)[1]), "+f"((c)[2]), "+f"((c)[3]) \
                 : "r"(a0), "r"(a1), "r"(a2), "r"(a3), "r"(b0), "r"(b1))

// blocked SW128 layout for a 128-row x 512-byte bf16 tile (64 atoms x 1KB)
__device__ __forceinline__ uint32_t tileoff(int r, int cb) {
    int b = ((r >> 3) + (cb >> 7) * 16) * 1024 + (r & 7) * 128 + (cb & 127);
    return (uint32_t)(b ^ ((b >> 3) & 0x70));
}

// ------------------------- top-k helpers -----------------------------------
__device__ __forceinline__ bool better(float v1, int i1, float v2, int i2) {
    return (v1 > v2) || (v1 == v2 && i1 < i2);
}

__device__ __forceinline__ void insert8(float tv[8], int ti[8], float v, int e) {
    if (better(v, e, tv[7], ti[7])) {
        tv[7] = v; ti[7] = e;
#pragma unroll
        for (int j = 7; j > 0; --j) {
            if (better(tv[j], ti[j], tv[j - 1], ti[j - 1])) {
                float fv = tv[j]; tv[j] = tv[j - 1]; tv[j - 1] = fv;
                int ii = ti[j]; ti[j] = ti[j - 1]; ti[j - 1] = ii;
            }
        }
    }
}

// packed sortable key: [31:15] order-preserving float bits, [14:0] 0x7FFF-eloc
__device__ __forceinline__ uint32_t sortkey(float v, int eloc) {
    uint32_t u = __float_as_uint(v);
    u ^= (uint32_t)((int32_t)u >> 31) | 0x80000000u;
    return (u & 0xFFFF8000u) | (uint32_t)(0x7FFF - eloc);
}

__device__ __forceinline__ void insert8u(uint32_t k[8], uint32_t key) {
    if (key > k[7]) {
        k[7] = key;
#pragma unroll
        for (int j = 7; j > 0; --j) {
            if (k[j] > k[j - 1]) { uint32_t t = k[j]; k[j] = k[j - 1]; k[j - 1] = t; }
        }
    }
}

__device__ __noinline__ void insert16u_slow(uint32_t* tk, uint32_t key) {
    int q = 15;
    while (q > 0 && key > tk[q - 1]) { tk[q] = tk[q - 1]; --q; }
    tk[q] = key;
}

// ------------------------- fused prep kernel -------------------------------
// [0,6272): entity bf16 pack; [6272,7296): spanmax/cls; [7296,7328): rowbias;
// [7328,7336): W1/W2 split-bf16 transpose prepack.
__global__ void k_prep(const float* __restrict__ emb, const float* __restrict__ ET,
                       const float* __restrict__ spanW, const float* __restrict__ spanb,
                       const float* __restrict__ W1, const float* __restrict__ W2,
                       float* __restrict__ out_cls) {
    int blk = blockIdx.x;
    if (blk < 6272) {
        int g = blk * 256 + threadIdx.x;   // one 16B output chunk
        int r = g >> 5, ch = g & 31;
        uint4 o = make_uint4(0u, 0u, 0u, 0u);
        if (r < NE) {
            const float4* s = (const float4*)&ET[(size_t)r * 256 + ch * 8];
            float4 v0 = s[0], v1 = s[1];
            __nv_bfloat162 p0 = {__float2bfloat16(v0.x), __float2bfloat16(v0.y)};
            __nv_bfloat162 p1 = {__float2bfloat16(v0.z), __float2bfloat16(v0.w)};
            __nv_bfloat162 p2 = {__float2bfloat16(v1.x), __float2bfloat16(v1.y)};
            __nv_bfloat162 p3 = {__float2bfloat16(v1.z), __float2bfloat16(v1.w)};
            o = make_uint4(*(uint32_t*)&p0, *(uint32_t*)&p1,
                           *(uint32_t*)&p2, *(uint32_t*)&p3);
        }
        size_t tile = (size_t)(r >> 7);
        *(uint4*)(g_ETraw + tile * 65536 + tileoff(r & 127, ch * 16)) = o;
    } else if (blk < 7296) {
        int g = (blk - 6272) * 256 + threadIdx.x;   // b*65536 + s*256 + h
        int h = g & 255, s = (g >> 8) & 255, b = g >> 16;
        float v0 = emb[g];
        float cur = v0;
        g_spanmax[g] = cur;
#pragma unroll
        for (int w = 1; w < 8; ++w) {
            if (s + w < 256) cur = fmaxf(cur, emb[((size_t)b * 256 + s + w) * 256 + h]);
            g_spanmax[(size_t)w * 262144 + g] = cur;
        }
        if (s == 0) out_cls[b * 256 + h] = v0;
    } else if (blk < 7328) {
        int bw = blk - 7296;
        int w = bw >> 2, b = bw & 3;
        int h = threadIdx.x;
        __shared__ float cls_s[256];
        cls_s[h] = emb[(size_t)b * 65536 + h];
        __syncthreads();
        float acc = spanb[h] + (float)(w + 1) * spanW[512 * 256 + h];
        for (int j = 0; j < 256; ++j)
            acc = fmaf(cls_s[j], spanW[(256 + j) * 256 + h], acc);
        g_rowbias[bw * 256 + h] = acc;
    } else {
        // W prepack: block t = (m, kh, nb); tile = 128 n_local x 128 kk,
        // hi bf16 at cb=2*kk, lo at cb=256+2*kk. Wt[n][k] = W[k][n].
        int t = blk - 7328;
        int m = t >> 2, kh = (t >> 1) & 1, nb = t & 1;
        const float* Ws = m ? W2 : W1;
        uint8_t* gt = g_Wp[m][kh * 2 + nb];
        for (int e = threadIdx.x; e < 8192; e += 256) {
            int n_l = e & 127, kp = e >> 7;       // kp = kk/2
            int k0 = kh * 128 + kp * 2;
            int n = nb * 128 + n_l;
            float w0 = Ws[(size_t)k0 * 256 + n];
            float w1 = Ws[(size_t)(k0 + 1) * 256 + n];
            __nv_bfloat16 h0 = __float2bfloat16(w0);
            __nv_bfloat16 h1 = __float2bfloat16(w1);
            __nv_bfloat162 hp = {h0, h1};
            __nv_bfloat162 lp = {__float2bfloat16(w0 - __bfloat162float(h0)),
                                 __float2bfloat16(w1 - __bfloat162float(h1))};
            *(uint32_t*)(gt + tileoff(n_l, kp * 4)) = *(uint32_t*)&hp;
            *(uint32_t*)(gt + tileoff(n_l, 256 + kp * 4)) = *(uint32_t*)&lp;
        }
    }
}

// ------------------------- FFMA GEMM (span MLP only) ------------------------

__device__ __forceinline__ void fill_a(float* a_sm, const float* __restrict__ A,
                                       int row0, int tid) {
#pragma unroll
    for (int it = 0; it < 16; ++it) {
        int f = tid + 256 * it;
        int r = f >> 6;
        int q = f & 63;
        float4 v = *(const float4*)&A[(size_t)(row0 + r) * 256 + 4 * q];
        a_sm[(4 * q + 0) * A_PAD + r] = v.x;
        a_sm[(4 * q + 1) * A_PAD + r] = v.y;
        a_sm[(4 * q + 2) * A_PAD + r] = v.z;
        a_sm[(4 * q + 3) * A_PAD + r] = v.w;
    }
}

__device__ __forceinline__ void fill_b(float* b_sm, const float* __restrict__ Bg,
                                       int ldb, int colBase, int kc, int tid) {
#pragma unroll
    for (int it = 0; it < 8; ++it) {
        int f = tid + 256 * it;
        int kk = f >> 5;
        int e4 = f & 31;
        int gc = colBase + 4 * e4;
        float4 v = *(const float4*)&Bg[((size_t)(kc * 64 + kk)) * ldb + gc];
        int cx = ((kk >> 3) & 7) << 2;
        *(float4*)&b_sm[kk * 128 + ((4 * e4) ^ cx)] = v;
    }
}

__global__ void __launch_bounds__(256, 2)
gemm_span(const float* __restrict__ A, const float* __restrict__ Bg,
          const float* __restrict__ bias, float* __restrict__ C) {
    extern __shared__ float sm[];
    float* a_sm = sm;
    float* b_sm = sm + 256 * A_PAD;
    int tid = threadIdx.x;

    int mt = blockIdx.x >> 1, nt = blockIdx.x & 1;
    int row0 = mt * 64;
    fill_a(a_sm, A, row0, tid);
    __syncthreads();

    int trow = tid >> 4, tc = tid & 15;
    int rb = trow * 4;

    float acc[4][8];
#pragma unroll
    for (int i = 0; i < 4; ++i)
#pragma unroll
        for (int j = 0; j < 8; ++j) acc[i][j] = 0.f;

#pragma unroll 1
    for (int kc = 0; kc < 4; ++kc) {
        if (kc) __syncthreads();
        fill_b(b_sm, Bg, 256, nt * 128, kc, tid);
        __syncthreads();
        const int cA = tc * 4;
        const int cB = 64 + tc * 4;
#pragma unroll 8
        for (int kk = 0; kk < 64; ++kk) {
            int kg = kc * 64 + kk;
            float a0 = a_sm[kg * A_PAD + rb + 0];
            float a1 = a_sm[kg * A_PAD + rb + 1];
            float a2 = a_sm[kg * A_PAD + rb + 2];
            float a3 = a_sm[kg * A_PAD + rb + 3];
            int cx = ((kk >> 3) & 7) << 2;
            const float4 b0 = *(const float4*)&b_sm[kk * 128 + (cA ^ cx)];
            const float4 b1 = *(const float4*)&b_sm[kk * 128 + (cB ^ cx)];
            float bj[8] = {b0.x, b0.y, b0.z, b0.w, b1.x, b1.y, b1.z, b1.w};
            float ai[4] = {a0, a1, a2, a3};
#pragma unroll
            for (int i = 0; i < 4; ++i)
#pragma unroll
                for (int j = 0; j < 8; ++j)
                    acc[i][j] = fmaf(ai[i], bj[j], acc[i][j]);
        }
    }

    int c0 = nt * 128 + tc * 4;
    int c1 = c0 + 64;
#pragma unroll
    for (int i = 0; i < 4; ++i) {
        int row = row0 + rb + i;
        const float* rbp = bias + ((row >> 8) * 256);
        size_t ro = (size_t)row * 256;
        float o[8];
#pragma unroll
        for (int j = 0; j < 4; ++j) {
            o[j] = acc[i][j] + rbp[c0 + j];
            o[4 + j] = acc[i][4 + j] + rbp[c1 + j];
        }
        *(float4*)&C[ro + c0] = make_float4(o[0], o[1], o[2], o[3]);
        *(float4*)&C[ro + c1] = make_float4(o[4], o[5], o[6], o[7]);
    }
}

// ------------------------- split-bf16 HMMA GEMM (Y, Z) ----------------------
// C[M,256] = A[M,256] @ W[256,256] via A_hi*W_hi + A_hi*W_lo + A_lo*W_hi.
// 1024 threads, 128 rows/CTA, two k-passes of 128.
// smem: A tile (hi|lo) 64KB @0, W nb0 64KB @64K, W nb1 64KB @128K, mbar @192K.

#define HG_SMEM (196608 + 64)

__global__ void __launch_bounds__(1024, 1)
k_hgemm(const float* __restrict__ A, const uint8_t* __restrict__ Wp,
        float* __restrict__ C, int rowmax) {
    extern __shared__ char rawsm[];
    char* smb = (char*)(((uintptr_t)rawsm + 1023) & ~(uintptr_t)1023);
    uint32_t sbase = smem_u32(smb);
    const uint32_t BAR = sbase + 196608;
    int tid = threadIdx.x;
    int w = tid >> 5, lane = tid & 31;
    int row0 = blockIdx.x * 128;

    if (tid == 0) MBAR_INIT(BAR, 1);

    // fragment addressing (same geometry as mma_topk)
    const int a_r = (w >> 2) * 16 + ((lane >> 3) & 1) * 8 + (lane & 7);
    const int a_cb0 = ((lane >> 4) & 1) * 16;
    const uint32_t aBase = sbase + (uint32_t)((a_r >> 3) * 1024 + (a_r & 7) * 128);
    const int n_l0 = ((w & 3) & 1) * 64 + ((lane >> 4) & 1) * 8 + (lane & 7);
    const int w_cb0 = ((lane >> 3) & 1) * 16;
    const uint32_t wBase = sbase + 65536 + ((w & 3) >> 1) * 65536
                         + (uint32_t)((n_l0 >> 3) * 1024 + (n_l0 & 7) * 128);
    uint32_t aOff[4], wOff[4];
#pragma unroll
    for (int j = 0; j < 4; ++j) {
        aOff[j] = (uint32_t)(j * 32 + a_cb0) ^ (uint32_t)((a_r & 7) << 4);
        wOff[j] = (uint32_t)(j * 32 + w_cb0) ^ (uint32_t)((n_l0 & 7) << 4);
    }

    float acc[4][8];
#pragma unroll
    for (int cs = 0; cs < 4; ++cs)
#pragma unroll
        for (int j = 0; j < 8; ++j) acc[cs][j] = 0.f;

#pragma unroll 1
    for (int pass = 0; pass < 2; ++pass) {
        if (pass) __syncthreads();   // smem reads of pass 0 complete

        // A half -> hi|lo bf16 tile. thread: row tid>>3, k chunk (tid&7)*16
        {
            int r = tid >> 3, k0 = (tid & 7) * 16;
            int rr = min(row0 + r, rowmax);
            const float* ap = A + (size_t)rr * 256 + pass * 128 + k0;
#pragma unroll
            for (int pq = 0; pq < 8; ++pq) {
                float2 v = *(const float2*)&ap[pq * 2];
                __nv_bfloat16 h0 = __float2bfloat16(v.x);
                __nv_bfloat16 h1 = __float2bfloat16(v.y);
                __nv_bfloat162 hp = {h0, h1};
                __nv_bfloat162 lp = {__float2bfloat16(v.x - __bfloat162float(h0)),
                                     __float2bfloat16(v.y - __bfloat162float(h1))};
                int k = k0 + pq * 2;
                STS32(sbase + tileoff(r, 2 * k), *(uint32_t*)&hp);
                STS32(sbase + tileoff(r, 256 + 2 * k), *(uint32_t*)&lp);
            }
        }
        if (tid == 0) {
            MBAR_EXPECT_TX(BAR, 131072u);
            BULK_LD(sbase + 65536, (const void*)(Wp + (size_t)(pass * 2) * 65536),
                    65536u, BAR);
            BULK_LD(sbase + 131072, (const void*)(Wp + (size_t)(pass * 2 + 1) * 65536),
                    65536u, BAR);
        }
        __syncthreads();          // A tile ready
        waitp(BAR, pass & 1);     // W tiles ready

#pragma unroll
        for (int ks = 0; ks < 8; ++ks) {
            const uint32_t kc = (uint32_t)((ks >> 2) * 16384);
            uint32_t ah0, ah1, ah2, ah3, al0, al1, al2, al3;
            LDMX4(ah0, ah1, ah2, ah3, aBase + kc + aOff[ks & 3]);
            LDMX4(al0, al1, al2, al3, aBase + (kc + 32768u) + aOff[ks & 3]);
#pragma unroll
            for (int cs = 0; cs < 4; ++cs) {
                uint32_t wa = wBase + (uint32_t)cs * 2048 + kc + wOff[ks & 3];
                uint32_t wh0, wh1, wh2, wh3, wl0, wl1, wl2, wl3;
                LDMX4(wh0, wh1, wh2, wh3, wa);
                LDMX4(wl0, wl1, wl2, wl3, wa + 32768u);
                MMA16816(acc[cs], ah0, ah1, ah2, ah3, wh0, wh1);
                MMA16816(acc[cs] + 4, ah0, ah1, ah2, ah3, wh2, wh3);
                MMA16816(acc[cs], ah0, ah1, ah2, ah3, wl0, wl1);
                MMA16816(acc[cs] + 4, ah0, ah1, ah2, ah3, wl2, wl3);
                MMA16816(acc[cs], al0, al1, al2, al3, wh0, wh1);
                MMA16816(acc[cs] + 4, al0, al1, al2, al3, wh2, wh3);
            }
        }
    }

    // epilogue: standard m16n8 C layout
    int r1 = row0 + (w >> 2) * 16 + (lane >> 2);
    int cb = (w & 3) * 64 + (lane & 3) * 2;
#pragma unroll
    for (int cs = 0; cs < 4; ++cs) {
        int c = cb + cs * 16;
        *(float2*)&C[(size_t)r1 * 256 + c] = make_float2(acc[cs][0], acc[cs][1]);
        *(float2*)&C[(size_t)r1 * 256 + c + 8] = make_float2(acc[cs][4], acc[cs][5]);
        *(float2*)&C[(size_t)(r1 + 8) * 256 + c] = make_float2(acc[cs][2], acc[cs][3]);
        *(float2*)&C[(size_t)(r1 + 8) * 256 + c + 8] = make_float2(acc[cs][6], acc[cs][7]);
    }
}

// ------------------------- bf16 mma sims + top-k filter --------------------
// grid (64 row-tiles, 2 esegs), 1024 threads (32 warps, 48% occ).

#define MK_SMEM (1024 + 196608 + 128)

__global__ void __launch_bounds__(1024, 1)
mma_topk(const float* __restrict__ spanrepr) {
    extern __shared__ char rawsm[];
    char* smb = (char*)(((uintptr_t)rawsm + 1023) & ~(uintptr_t)1023);
    uint32_t sbase = smem_u32(smb);
    const uint32_t BARS = sbase + 196608;
    int tid = threadIdx.x;
    int w = tid >> 5, lane = tid & 31;

    int row0 = blockIdx.x * 128;
    int ebase = blockIdx.y * (NTILES_SEG * 128);
    int tbase = blockIdx.y * NTILES_SEG;

    if (tid == 0) {
        MBAR_INIT(BARS + 0, 1);  MBAR_INIT(BARS + 8, 1);    // full (tx-based)
        MBAR_INIT(BARS + 16, 32); MBAR_INIT(BARS + 24, 32); // empty (32 warps)
    }

    // A tile: span_repr rows -> bf16 blocked SW128 layout
    for (int i = tid; i < 128 * 128; i += 1024) {
        int r = i >> 7, c = (i & 127) * 2;
        float2 v = *(const float2*)&spanrepr[(size_t)(row0 + r) * 256 + c];
        __nv_bfloat162 bb = {__float2bfloat16(v.x), __float2bfloat16(v.y)};
        STS32(sbase + tileoff(r, c * 2), *(uint32_t*)&bb);
    }
    __syncthreads();

    if (tid == 0) {
        MBAR_EXPECT_TX(BARS + 0, 65536u);
        BULK_LD(sbase + 65536, (const void*)(g_ETraw + (size_t)tbase * 65536),
                65536u, BARS + 0);
    }

    const int wr = (w >> 2) * 16;
    const int wc = (w & 3) * 32;

    uint32_t k1[8], k2[8];
#pragma unroll
    for (int j = 0; j < 8; ++j) { k1[j] = 0u; k2[j] = 0u; }

    const int a_r = wr + ((lane >> 3) & 1) * 8 + (lane & 7);
    const int a_cb = ((lane >> 4) & 1) * 16;
    const int b_rbase = wc + ((lane >> 4) & 1) * 8 + (lane & 7);
    const int b_cb = ((lane >> 3) & 1) * 16;

    const uint32_t aBase = sbase + (uint32_t)((a_r >> 3) * 1024 + (a_r & 7) * 128);
    const uint32_t aMask = (uint32_t)((a_r & 7) << 4);
    const uint32_t bBaseRel = (uint32_t)((b_rbase >> 3) * 1024 + (b_rbase & 7) * 128);
    const uint32_t bMask = (uint32_t)((b_rbase & 7) << 4);
    uint32_t aOff[4], bOff[4];
#pragma unroll
    for (int j = 0; j < 4; ++j) {
        aOff[j] = (uint32_t)((j * 32 + a_cb)) ^ aMask;
        bOff[j] = (uint32_t)((j * 32 + b_cb)) ^ bMask;
    }

#pragma unroll 1
    for (int i = 0; i < NTILES_SEG; ++i) {
        int s = i & 1, n = i >> 1;
        if (tid == 0 && i + 1 < NTILES_SEG) {
            int j = i + 1, s2 = j & 1;
            if (j >= 2) waitp(BARS + 16 + s2 * 8, ((j >> 1) + 1) & 1);
            MBAR_EXPECT_TX(BARS + 0 + s2 * 8, 65536u);
            BULK_LD(sbase + 65536 + s2 * 65536,
                    (const void*)(g_ETraw + (size_t)(tbase + j) * 65536),
                    65536u, BARS + 0 + s2 * 8);
        }
        waitp(BARS + 0 + s * 8, n & 1);

        uint32_t bBase = sbase + 65536 + s * 65536 + bBaseRel;
        float acc[4][4];
#pragma unroll
        for (int q = 0; q < 4; ++q)
#pragma unroll
            for (int j = 0; j < 4; ++j) acc[q][j] = 0.f;

#pragma unroll
        for (int ks = 0; ks < 16; ++ks) {
            const uint32_t kc = (uint32_t)((ks >> 2) * 16384);
            uint32_t a0, a1, a2, a3;
            LDMX4(a0, a1, a2, a3, aBase + kc + aOff[ks & 3]);
#pragma unroll
            for (int p = 0; p < 2; ++p) {
                uint32_t b0, b1, b2, b3;
                LDMX4(b0, b1, b2, b3, bBase + (kc + p * 2048) + bOff[ks & 3]);
                MMA16816(acc[2 * p], a0, a1, a2, a3, b0, b1);
                MMA16816(acc[2 * p + 1], a0, a1, a2, a3, b2, b3);
            }
        }
        __syncwarp();
        if (lane == 0) MBAR_ARRIVE(BARS + 16 + s * 8);  // acc in regs -> stage free

        int ebloc = i * 128 + wc + (lane & 3) * 2;
#pragma unroll
        for (int q = 0; q < 4; ++q) {
            int el = ebloc + q * 8;
            insert8u(k1, sortkey(acc[q][0], el));
            insert8u(k1, sortkey(acc[q][1], el + 1));
            insert8u(k2, sortkey(acc[q][2], el));
            insert8u(k2, sortkey(acc[q][3], el + 1));
        }
    }

    // -------- CTA merge: 16 streams/row -> top-16/row --------
    __syncthreads();
    uint32_t* mk = (uint32_t*)(smb + 65536);      // [128][128] keys (64KB)
    int sid = (w & 3) * 4 + (lane & 3);
    int r1 = wr + (lane >> 2), r2 = r1 + 8;
#pragma unroll
    for (int j = 0; j < 8; ++j) {
        mk[r1 * 128 + sid * 8 + j] = k1[j];
        mk[r2 * 128 + sid * 8 + j] = k2[j];
    }
    __syncthreads();
    if (tid < 128) {
        uint32_t tk[16];
#pragma unroll
        for (int j = 0; j < 16; ++j) tk[j] = 0u;
        for (int q = 0; q < 128; ++q) {
            uint32_t key = mk[tid * 128 + q];
            if (key > tk[15]) insert16u_slow(tk, key);
        }
        int* cp = &g_cand[((size_t)blockIdx.y * 8192 + row0 + tid) * 16];
#pragma unroll
        for (int j = 0; j < 16; ++j) {
            int e = ebase + (0x7FFF - (int)(tk[j] & 0x7FFFu));
            cp[j] = (e < NE) ? e : 0;   // clamp (padded sims never win anyway)
        }
    }
}

// ------------------------- exact fp32 refine -------------------------------
__global__ void __launch_bounds__(256)
k_refine(const float* __restrict__ spanrepr, const float* __restrict__ ET) {
    int warp = threadIdx.x >> 5, lane = threadIdx.x & 31;
    int row = blockIdx.x * 8 + warp;

    __shared__ float sims[8][32];
    __shared__ int cidx[8][32];

    if (lane < 16) {
        cidx[warp][lane] = g_cand[((size_t)0 * 8192 + row) * 16 + lane];
        cidx[warp][16 + lane] = g_cand[((size_t)1 * 8192 + row) * 16 + lane];
    }
    float4 a0 = *(const float4*)&spanrepr[(size_t)row * 256 + lane * 8];
    float4 a1 = *(const float4*)&spanrepr[(size_t)row * 256 + lane * 8 + 4];
    __syncwarp();

#pragma unroll 1
    for (int c = 0; c < 32; ++c) {
        int idx = cidx[warp][c];
        const float4* ep = (const float4*)&ET[(size_t)idx * 256 + lane * 8];
        float4 e0 = ep[0], e1 = ep[1];
        float d = a0.x * e0.x + a0.y * e0.y + a0.z * e0.z + a0.w * e0.w
                + a1.x * e1.x + a1.y * e1.y + a1.z * e1.z + a1.w * e1.w;
#pragma unroll
        for (int o = 16; o; o >>= 1) d += __shfl_xor_sync(0xFFFFFFFFu, d, o);
        if (lane == 0) sims[warp][c] = d;
    }
    __syncwarp();
    if (lane == 0) {
        float tv[8]; int ti[8];
#pragma unroll
        for (int j = 0; j < 8; ++j) { tv[j] = -FLT_MAX; ti[j] = 0x7FFFFFFF; }
        for (int c = 0; c < 32; ++c) insert8(tv, ti, sims[warp][c], cidx[warp][c]);
#pragma unroll
        for (int j = 0; j < 8; ++j) g_topk[(size_t)row * 8 + j] = ti[j];
    }
}

// ------------------------- GCN fused stages ---------------------------------
__global__ void k_gather_mix(const float* __restrict__ b1) {
    int n = blockIdx.x, h = threadIdx.x;
    __shared__ int id[8];
    if (h < 8) id[h] = g_topk[n * 8 + h];
    __syncthreads();
    float bb = b1[h];
    float y0 = g_ybuf[(size_t)id[0] * 256 + h];
    float s = 0.f;
    float* outb = g_hbuf + (size_t)n * 8 * 256 + h;
#pragma unroll
    for (int j = 1; j < 8; ++j) {
        float yj = g_ybuf[(size_t)id[j] * 256 + h];
        s += yj;
        outb[j * 256] = fmaxf(0.25f * y0 + 0.5f * yj + bb, 0.f);
    }
    outb[0] = fmaxf(0.125f * y0 + 0.25f * s + bb, 0.f);
}

__global__ void k_mix_out(const float* __restrict__ b2, float* __restrict__ out_sub) {
    int n = blockIdx.x, h = threadIdx.x;
    const float* inb = g_zbuf + (size_t)n * 8 * 256 + h;
    float* outb = out_sub + (size_t)n * 8 * 256 + h;
    float bb = b2[h];
    float z0 = inb[0];
    float s = 0.f;
#pragma unroll
    for (int j = 1; j < 8; ++j) {
        float zj = inb[j * 256];
        s += zj;
        outb[j * 256] = 0.25f * z0 + 0.5f * zj + bb;
    }
    outb[0] = 0.125f * z0 + 0.25f * s + bb;
}

// ------------------------- host --------------------------------------------
extern "C" void kernel_launch(void* const* d_in, const int* in_sizes, int n_in,
                              void* d_out, int out_size) {
    const float* emb = (const float*)d_in[0];
    const float* ET = (const float*)d_in[1];
    const float* spanW = (const float*)d_in[2];
    const float* spanb = (const float*)d_in[3];
    const float* W1 = (const float*)d_in[4];
    const float* b1 = (const float*)d_in[5];
    const float* W2 = (const float*)d_in[6];
    const float* b2 = (const float*)d_in[7];

    float* out = (float*)d_out;
    float* out_cls = out;                       // 4*256
    float* out_spanrepr = out + 1024;           // 8192*256
    float* out_sub = out + 1024 + 8192 * 256;   // 65536*256

    float *spanmax, *rowbias, *ybuf, *hbuf, *zbuf;
    uint8_t* wp;
    cudaGetSymbolAddress((void**)&spanmax, g_spanmax);
    cudaGetSymbolAddress((void**)&rowbias, g_rowbias);
    cudaGetSymbolAddress((void**)&ybuf, g_ybuf);
    cudaGetSymbolAddress((void**)&hbuf, g_hbuf);
    cudaGetSymbolAddress((void**)&zbuf, g_zbuf);
    cudaGetSymbolAddress((void**)&wp, g_Wp);

    cudaFuncSetAttribute(gemm_span, cudaFuncAttributeMaxDynamicSharedMemorySize, SMEM_BYTES);
    cudaFuncSetAttribute(mma_topk, cudaFuncAttributeMaxDynamicSharedMemorySize, MK_SMEM);
    cudaFuncSetAttribute(k_hgemm, cudaFuncAttributeMaxDynamicSharedMemorySize, HG_SMEM + 1024);

    // 1) fused prep: entity bf16 pack + cls/spanmax + rowbias + W split-pack
    k_prep<<<7336, TPB>>>(emb, ET, spanW, spanb, W1, W2, out_cls);
    // 2) span_repr = spanmax @ W[0:256] + rowbias  (FFMA)
    gemm_span<<<256, TPB, SMEM_BYTES>>>(spanmax, spanW, rowbias, out_spanrepr);
    // 3) Y = ET @ W1  (split-bf16 HMMA)
    k_hgemm<<<NEP / 128, 1024, HG_SMEM + 1024>>>(ET, wp, ybuf, NE - 1);
    // 4) bf16 mma sims + per-eseg top-16 candidate filter
    mma_topk<<<dim3(64, 2), 1024, MK_SMEM>>>(out_spanrepr);
    // 5) exact fp32 refine -> sorted top-8
    k_refine<<<1024, 256>>>(out_spanrepr, ET);
    // 6) h = relu(mix(Y[topk]) + b1)
    k_gather_mix<<<NROWS, TPB>>>(b1);
    // 7) Z = h @ W2  (split-bf16 HMMA)
    k_hgemm<<<512, 1024, HG_SMEM + 1024>>>(hbuf, wp + 4 * 65536, zbuf, 65535);
    // 8) out_sub = mix(Z) + b2
    k_mix_out<<<NROWS, TPB>>>(b2, out_sub);

    (void)in_sizes; (void)n_in; (void)out_size;
}

// round 14
// speedup vs baseline: 1.3513x; 1.0915x over previous
#include <cuda_runtime.h>
#include <cuda_bf16.h>
#include <cstdint>
#include <cfloat>

// ---------------------------------------------------------------------------
// SpanModel: cls, span_repr = spanMLP(spanmax,cls,width), top8(entity sims),
// star-GCN (2 layers). sims via bf16 mma.sync filter + exact fp32 refine.
// Y=ET@W1 hgemm runs fused in the same launch as the topk filter (idle-SM
// overlap); Z=h@W2 hgemm fuses the star-mix epilogue.
// ---------------------------------------------------------------------------

#define TPB 256
#define A_PAD 65
#define SMEM_FLOATS (256 * A_PAD + 64 * 128)
#define SMEM_BYTES (SMEM_FLOATS * 4)

static const int NE = 50000;
static const int NEP = 50176;        // padded to 392*128
static const int NROWS = 8192;       // Wmax*B*S
static const int NTILES_SEG = 196;   // tiles per entity segment (392/2)

// ------------------------- scratch (device globals) -----------------------
__device__ __align__(16) uint8_t g_ETraw[(size_t)NEP * 512]; // bf16, tile-blocked SW128
__device__ __align__(16) uint8_t g_Wp[2][4][65536]; // W1/W2 split-bf16 [m][kh*2+nb]
__device__ float g_spanmax[8L * 1024 * 256];   // [w][b][s][h]
__device__ float g_rowbias[32 * 256];          // per (w,b) bias row
__device__ int   g_cand[2L * 8192 * 16];       // candidate indices per eseg
__device__ int   g_topk[8192L * 8];            // final sorted top-8 indices
__device__ float g_ybuf[(size_t)NEP * 256];    // Y = ET @ W1
__device__ float g_hbuf[65536L * 256];         // relu hidden

// ------------------------- PTX helpers -------------------------------------
__device__ __forceinline__ uint32_t smem_u32(const void* p) {
    uint32_t a;
    asm("{ .reg .u64 t; cvta.to.shared.u64 t, %1; cvt.u32.u64 %0, t; }"
        : "=r"(a) : "l"(p));
    return a;
}

#define STS32(addr, v) \
    asm volatile("st.shared.b32 [%0], %1;" :: "r"(addr), "r"(v) : "memory")

#define MBAR_INIT(addr, cnt) \
    asm volatile("mbarrier.init.shared.b64 [%0], %1;" :: "r"(addr), "r"(cnt) : "memory")
#define MBAR_ARRIVE(addr) \
    asm volatile("mbarrier.arrive.shared.b64 _, [%0];" :: "r"(addr) : "memory")
#define MBAR_EXPECT_TX(addr, bytes) \
    asm volatile("mbarrier.arrive.expect_tx.shared.b64 _, [%0], %1;" \
                 :: "r"(addr), "r"(bytes) : "memory")
#define BULK_LD(dst, src, bytes, mbar) \
    asm volatile("cp.async.bulk.shared::cta.global.mbarrier::complete_tx::bytes " \
                 "[%0], [%1], %2, [%3];" \
                 :: "r"(dst), "l"(src), "r"(bytes), "r"(mbar) : "memory")

__device__ __forceinline__ void waitp(uint32_t mbar, uint32_t phase) {
    asm volatile(
        "{\n\t.reg .pred P;\n\t"
        "WL%=:\n\t"
        "mbarrier.try_wait.parity.acquire.cta.shared::cta.b64 P, [%0], %1, 0x989680;\n\t"
        "@P bra WD%=;\n\t"
        "bra WL%=;\n\t"
        "WD%=:\n\t}"
        :: "r"(mbar), "r"(phase) : "memory");
}

#define LDMX4(r0, r1, r2, r3, addr) \
    asm volatile("ldmatrix.sync.aligned.m8n8.x4.shared.b16 {%0,%1,%2,%3}, [%4];" \
                 : "=r"(r0), "=r"(r1), "=r"(r2), "=r"(r3) : "r"(addr))

#define MMA16816(c, a0, a1, a2, a3, b0, b1) \
    asm volatile("mma.sync.aligned.m16n8k16.row.col.f32.bf16.bf16.f32 " \
                 "{%0,%1,%2,%3}, {%4,%5,%6,%7}, {%8,%9}, {%0,%1,%2,%3};" \
                 : "+f"((c)[0]), "+f"((c)[1]), "+f"((c)[2]), "+f"((c)[3]) \
                 : "r"(a0), "r"(a1), "r"(a2), "r"(a3), "r"(b0), "r"(b1))

// blocked SW128 layout for a 128-row x 512-byte bf16 tile (64 atoms x 1KB)
__device__ __forceinline__ uint32_t tileoff(int r, int cb) {
    int b = ((r >> 3) + (cb >> 7) * 16) * 1024 + (r & 7) * 128 + (cb & 127);
    return (uint32_t)(b ^ ((b >> 3) & 0x70));
}

// ------------------------- top-k helpers -----------------------------------
__device__ __forceinline__ bool better(float v1, int i1, float v2, int i2) {
    return (v1 > v2) || (v1 == v2 && i1 < i2);
}

__device__ __forceinline__ void insert8(float tv[8], int ti[8], float v, int e) {
    if (better(v, e, tv[7], ti[7])) {
        tv[7] = v; ti[7] = e;
#pragma unroll
        for (int j = 7; j > 0; --j) {
            if (better(tv[j], ti[j], tv[j - 1], ti[j - 1])) {
                float fv = tv[j]; tv[j] = tv[j - 1]; tv[j - 1] = fv;
                int ii = ti[j]; ti[j] = ti[j - 1]; ti[j - 1] = ii;
            }
        }
    }
}

// packed sortable key: [31:15] order-preserving float bits, [14:0] 0x7FFF-eloc
__device__ __forceinline__ uint32_t sortkey(float v, int eloc) {
    uint32_t u = __float_as_uint(v);
    u ^= (uint32_t)((int32_t)u >> 31) | 0x80000000u;
    return (u & 0xFFFF8000u) | (uint32_t)(0x7FFF - eloc);
}

__device__ __forceinline__ void insert8u(uint32_t k[8], uint32_t key) {
    if (key > k[7]) {
        k[7] = key;
#pragma unroll
        for (int j = 7; j > 0; --j) {
            if (k[j] > k[j - 1]) { uint32_t t = k[j]; k[j] = k[j - 1]; k[j - 1] = t; }
        }
    }
}

__device__ __noinline__ void insert16u_slow(uint32_t* tk, uint32_t key) {
    int q = 15;
    while (q > 0 && key > tk[q - 1]) { tk[q] = tk[q - 1]; --q; }
    tk[q] = key;
}

// ------------------------- fused prep kernel -------------------------------
__global__ void k_prep(const float* __restrict__ emb, const float* __restrict__ ET,
                       const float* __restrict__ spanW, const float* __restrict__ spanb,
                       const float* __restrict__ W1, const float* __restrict__ W2,
                       float* __restrict__ out_cls) {
    int blk = blockIdx.x;
    if (blk < 6272) {
        int g = blk * 256 + threadIdx.x;   // one 16B output chunk
        int r = g >> 5, ch = g & 31;
        uint4 o = make_uint4(0u, 0u, 0u, 0u);
        if (r < NE) {
            const float4* s = (const float4*)&ET[(size_t)r * 256 + ch * 8];
            float4 v0 = s[0], v1 = s[1];
            __nv_bfloat162 p0 = {__float2bfloat16(v0.x), __float2bfloat16(v0.y)};
            __nv_bfloat162 p1 = {__float2bfloat16(v0.z), __float2bfloat16(v0.w)};
            __nv_bfloat162 p2 = {__float2bfloat16(v1.x), __float2bfloat16(v1.y)};
            __nv_bfloat162 p3 = {__float2bfloat16(v1.z), __float2bfloat16(v1.w)};
            o = make_uint4(*(uint32_t*)&p0, *(uint32_t*)&p1,
                           *(uint32_t*)&p2, *(uint32_t*)&p3);
        }
        size_t tile = (size_t)(r >> 7);
        *(uint4*)(g_ETraw + tile * 65536 + tileoff(r & 127, ch * 16)) = o;
    } else if (blk < 7296) {
        int g = (blk - 6272) * 256 + threadIdx.x;   // b*65536 + s*256 + h
        int h = g & 255, s = (g >> 8) & 255, b = g >> 16;
        float v0 = emb[g];
        float cur = v0;
        g_spanmax[g] = cur;
#pragma unroll
        for (int w = 1; w < 8; ++w) {
            if (s + w < 256) cur = fmaxf(cur, emb[((size_t)b * 256 + s + w) * 256 + h]);
            g_spanmax[(size_t)w * 262144 + g] = cur;
        }
        if (s == 0) out_cls[b * 256 + h] = v0;
    } else if (blk < 7328) {
        int bw = blk - 7296;
        int w = bw >> 2, b = bw & 3;
        int h = threadIdx.x;
        __shared__ float cls_s[256];
        cls_s[h] = emb[(size_t)b * 65536 + h];
        __syncthreads();
        float acc = spanb[h] + (float)(w + 1) * spanW[512 * 256 + h];
        for (int j = 0; j < 256; ++j)
            acc = fmaf(cls_s[j], spanW[(256 + j) * 256 + h], acc);
        g_rowbias[bw * 256 + h] = acc;
    } else {
        // W prepack: block t = (m, kh, nb); tile = 128 n_local x 128 kk,
        // hi bf16 at cb=2*kk, lo at cb=256+2*kk. Wt[n][k] = W[k][n].
        int t = blk - 7328;
        int m = t >> 2, kh = (t >> 1) & 1, nb = t & 1;
        const float* Ws = m ? W2 : W1;
        uint8_t* gt = g_Wp[m][kh * 2 + nb];
        for (int e = threadIdx.x; e < 8192; e += 256) {
            int n_l = e & 127, kp = e >> 7;       // kp = kk/2
            int k0 = kh * 128 + kp * 2;
            int n = nb * 128 + n_l;
            float w0 = Ws[(size_t)k0 * 256 + n];
            float w1 = Ws[(size_t)(k0 + 1) * 256 + n];
            __nv_bfloat16 h0 = __float2bfloat16(w0);
            __nv_bfloat16 h1 = __float2bfloat16(w1);
            __nv_bfloat162 hp = {h0, h1};
            __nv_bfloat162 lp = {__float2bfloat16(w0 - __bfloat162float(h0)),
                                 __float2bfloat16(w1 - __bfloat162float(h1))};
            *(uint32_t*)(gt + tileoff(n_l, kp * 4)) = *(uint32_t*)&hp;
            *(uint32_t*)(gt + tileoff(n_l, 256 + kp * 4)) = *(uint32_t*)&lp;
        }
    }
}

// ------------------------- FFMA GEMM (span MLP only) ------------------------

__device__ __forceinline__ void fill_a(float* a_sm, const float* __restrict__ A,
                                       int row0, int tid) {
#pragma unroll
    for (int it = 0; it < 16; ++it) {
        int f = tid + 256 * it;
        int r = f >> 6;
        int q = f & 63;
        float4 v = *(const float4*)&A[(size_t)(row0 + r) * 256 + 4 * q];
        a_sm[(4 * q + 0) * A_PAD + r] = v.x;
        a_sm[(4 * q + 1) * A_PAD + r] = v.y;
        a_sm[(4 * q + 2) * A_PAD + r] = v.z;
        a_sm[(4 * q + 3) * A_PAD + r] = v.w;
    }
}

__device__ __forceinline__ void fill_b(float* b_sm, const float* __restrict__ Bg,
                                       int ldb, int colBase, int kc, int tid) {
#pragma unroll
    for (int it = 0; it < 8; ++it) {
        int f = tid + 256 * it;
        int kk = f >> 5;
        int e4 = f & 31;
        int gc = colBase + 4 * e4;
        float4 v = *(const float4*)&Bg[((size_t)(kc * 64 + kk)) * ldb + gc];
        int cx = ((kk >> 3) & 7) << 2;
        *(float4*)&b_sm[kk * 128 + ((4 * e4) ^ cx)] = v;
    }
}

__global__ void __launch_bounds__(256, 2)
gemm_span(const float* __restrict__ A, const float* __restrict__ Bg,
          const float* __restrict__ bias, float* __restrict__ C) {
    extern __shared__ float sm[];
    float* a_sm = sm;
    float* b_sm = sm + 256 * A_PAD;
    int tid = threadIdx.x;

    int mt = blockIdx.x >> 1, nt = blockIdx.x & 1;
    int row0 = mt * 64;
    fill_a(a_sm, A, row0, tid);
    __syncthreads();

    int trow = tid >> 4, tc = tid & 15;
    int rb = trow * 4;

    float acc[4][8];
#pragma unroll
    for (int i = 0; i < 4; ++i)
#pragma unroll
        for (int j = 0; j < 8; ++j) acc[i][j] = 0.f;

#pragma unroll 1
    for (int kc = 0; kc < 4; ++kc) {
        if (kc) __syncthreads();
        fill_b(b_sm, Bg, 256, nt * 128, kc, tid);
        __syncthreads();
        const int cA = tc * 4;
        const int cB = 64 + tc * 4;
#pragma unroll 8
        for (int kk = 0; kk < 64; ++kk) {
            int kg = kc * 64 + kk;
            float a0 = a_sm[kg * A_PAD + rb + 0];
            float a1 = a_sm[kg * A_PAD + rb + 1];
            float a2 = a_sm[kg * A_PAD + rb + 2];
            float a3 = a_sm[kg * A_PAD + rb + 3];
            int cx = ((kk >> 3) & 7) << 2;
            const float4 b0 = *(const float4*)&b_sm[kk * 128 + (cA ^ cx)];
            const float4 b1 = *(const float4*)&b_sm[kk * 128 + (cB ^ cx)];
            float bj[8] = {b0.x, b0.y, b0.z, b0.w, b1.x, b1.y, b1.z, b1.w};
            float ai[4] = {a0, a1, a2, a3};
#pragma unroll
            for (int i = 0; i < 4; ++i)
#pragma unroll
                for (int j = 0; j < 8; ++j)
                    acc[i][j] = fmaf(ai[i], bj[j], acc[i][j]);
        }
    }

    int c0 = nt * 128 + tc * 4;
    int c1 = c0 + 64;
#pragma unroll
    for (int i = 0; i < 4; ++i) {
        int row = row0 + rb + i;
        const float* rbp = bias + ((row >> 8) * 256);
        size_t ro = (size_t)row * 256;
        float o[8];
#pragma unroll
        for (int j = 0; j < 4; ++j) {
            o[j] = acc[i][j] + rbp[c0 + j];
            o[4 + j] = acc[i][4 + j] + rbp[c1 + j];
        }
        *(float4*)&C[ro + c0] = make_float4(o[0], o[1], o[2], o[3]);
        *(float4*)&C[ro + c1] = make_float4(o[4], o[5], o[6], o[7]);
    }
}

// ------------------------- split-bf16 HMMA GEMM body ------------------------
// C[M,256] = A[M,256] @ W[256,256] via A_hi*W_hi + A_hi*W_lo + A_lo*W_hi.
// EPI=0: plain store; EPI=1: star-mix + bias -> C (warp's 16 rows = 2 subgraphs)

#define HG_SMEM (196608 + 64)

template <int EPI>
__device__ void body_hgemm(uint32_t sbase, int blk,
                           const float* __restrict__ A, const uint8_t* __restrict__ Wp,
                           const float* __restrict__ bias, float* __restrict__ C,
                           int rowmax) {
    const uint32_t BAR = sbase + 196608;
    int tid = threadIdx.x;
    int w = tid >> 5, lane = tid & 31;
    int row0 = blk * 128;

    if (tid == 0) MBAR_INIT(BAR, 1);

    const int a_r = (w >> 2) * 16 + ((lane >> 3) & 1) * 8 + (lane & 7);
    const int a_cb0 = ((lane >> 4) & 1) * 16;
    const uint32_t aBase = sbase + (uint32_t)((a_r >> 3) * 1024 + (a_r & 7) * 128);
    const int n_l0 = ((w & 3) & 1) * 64 + ((lane >> 4) & 1) * 8 + (lane & 7);
    const int w_cb0 = ((lane >> 3) & 1) * 16;
    const uint32_t wBase = sbase + 65536 + ((w & 3) >> 1) * 65536
                         + (uint32_t)((n_l0 >> 3) * 1024 + (n_l0 & 7) * 128);
    uint32_t aOff[4], wOff[4];
#pragma unroll
    for (int j = 0; j < 4; ++j) {
        aOff[j] = (uint32_t)(j * 32 + a_cb0) ^ (uint32_t)((a_r & 7) << 4);
        wOff[j] = (uint32_t)(j * 32 + w_cb0) ^ (uint32_t)((n_l0 & 7) << 4);
    }

    float acc[4][8];
#pragma unroll
    for (int cs = 0; cs < 4; ++cs)
#pragma unroll
        for (int j = 0; j < 8; ++j) acc[cs][j] = 0.f;

#pragma unroll 1
    for (int pass = 0; pass < 2; ++pass) {
        if (pass) __syncthreads();   // smem reads of pass 0 complete

        {
            int r = tid >> 3, k0 = (tid & 7) * 16;
            int rr = min(row0 + r, rowmax);
            const float* ap = A + (size_t)rr * 256 + pass * 128 + k0;
#pragma unroll
            for (int pq = 0; pq < 8; ++pq) {
                float2 v = *(const float2*)&ap[pq * 2];
                __nv_bfloat16 h0 = __float2bfloat16(v.x);
                __nv_bfloat16 h1 = __float2bfloat16(v.y);
                __nv_bfloat162 hp = {h0, h1};
                __nv_bfloat162 lp = {__float2bfloat16(v.x - __bfloat162float(h0)),
                                     __float2bfloat16(v.y - __bfloat162float(h1))};
                int k = k0 + pq * 2;
                STS32(sbase + tileoff(r, 2 * k), *(uint32_t*)&hp);
                STS32(sbase + tileoff(r, 256 + 2 * k), *(uint32_t*)&lp);
            }
        }
        if (tid == 0) {
            MBAR_EXPECT_TX(BAR, 131072u);
            BULK_LD(sbase + 65536, (const void*)(Wp + (size_t)(pass * 2) * 65536),
                    65536u, BAR);
            BULK_LD(sbase + 131072, (const void*)(Wp + (size_t)(pass * 2 + 1) * 65536),
                    65536u, BAR);
        }
        __syncthreads();          // A tile ready
        waitp(BAR, pass & 1);     // W tiles ready

#pragma unroll
        for (int ks = 0; ks < 8; ++ks) {
            const uint32_t kc = (uint32_t)((ks >> 2) * 16384);
            uint32_t ah0, ah1, ah2, ah3, al0, al1, al2, al3;
            LDMX4(ah0, ah1, ah2, ah3, aBase + kc + aOff[ks & 3]);
            LDMX4(al0, al1, al2, al3, aBase + (kc + 32768u) + aOff[ks & 3]);
#pragma unroll
            for (int cs = 0; cs < 4; ++cs) {
                uint32_t wa = wBase + (uint32_t)cs * 2048 + kc + wOff[ks & 3];
                uint32_t wh0, wh1, wh2, wh3, wl0, wl1, wl2, wl3;
                LDMX4(wh0, wh1, wh2, wh3, wa);
                LDMX4(wl0, wl1, wl2, wl3, wa + 32768u);
                MMA16816(acc[cs], ah0, ah1, ah2, ah3, wh0, wh1);
                MMA16816(acc[cs] + 4, ah0, ah1, ah2, ah3, wh2, wh3);
                MMA16816(acc[cs], ah0, ah1, ah2, ah3, wl0, wl1);
                MMA16816(acc[cs] + 4, ah0, ah1, ah2, ah3, wl2, wl3);
                MMA16816(acc[cs], al0, al1, al2, al3, wh0, wh1);
                MMA16816(acc[cs] + 4, al0, al1, al2, al3, wh2, wh3);
            }
        }
    }

    if (EPI == 0) {
        int r1 = row0 + (w >> 2) * 16 + (lane >> 2);
        int cb = (w & 3) * 64 + (lane & 3) * 2;
#pragma unroll
        for (int cs = 0; cs < 4; ++cs) {
            int c = cb + cs * 16;
            *(float2*)&C[(size_t)r1 * 256 + c] = make_float2(acc[cs][0], acc[cs][1]);
            *(float2*)&C[(size_t)r1 * 256 + c + 8] = make_float2(acc[cs][4], acc[cs][5]);
            *(float2*)&C[(size_t)(r1 + 8) * 256 + c] = make_float2(acc[cs][2], acc[cs][3]);
            *(float2*)&C[(size_t)(r1 + 8) * 256 + c + 8] = make_float2(acc[cs][6], acc[cs][7]);
        }
    } else {
        // fused star-mix + bias: warp rows [g,g+16) = subgraphs g/8, g/8+1
        int g = row0 + (w >> 2) * 16;
        int j = lane >> 2;                 // local row within subgraph
        int cb = (w & 3) * 64 + (lane & 3) * 2;
#pragma unroll
        for (int cs = 0; cs < 4; ++cs) {
            int c = cb + cs * 16;
            float2 bA = *(const float2*)&bias[c];
            float2 bB = *(const float2*)&bias[c + 8];
#pragma unroll
            for (int half = 0; half < 2; ++half) {
                int row = g + half * 8 + j;
#pragma unroll
                for (int pp = 0; pp < 2; ++pp) {
                    float v0 = acc[cs][half * 2 + pp * 4];
                    float v1 = acc[cs][half * 2 + pp * 4 + 1];
                    float S0 = v0, S1 = v1;
#pragma unroll
                    for (int o = 4; o <= 16; o <<= 1) {
                        S0 += __shfl_xor_sync(0xFFFFFFFFu, S0, o);
                        S1 += __shfl_xor_sync(0xFFFFFFFFu, S1, o);
                    }
                    float z00 = __shfl_sync(0xFFFFFFFFu, v0, lane & 3);
                    float z01 = __shfl_sync(0xFFFFFFFFu, v1, lane & 3);
                    float o0, o1;
                    if (j == 0) {
                        o0 = 0.25f * S0 - 0.125f * z00;
                        o1 = 0.25f * S1 - 0.125f * z01;
                    } else {
                        o0 = 0.25f * z00 + 0.5f * v0;
                        o1 = 0.25f * z01 + 0.5f * v1;
                    }
                    o0 += pp ? bB.x : bA.x;
                    o1 += pp ? bB.y : bA.y;
                    *(float2*)&C[(size_t)row * 256 + c + pp * 8] = make_float2(o0, o1);
                }
            }
        }
    }
}

// ------------------------- bf16 mma sims + top-k body -----------------------

__device__ void body_topk(uint32_t sbase, char* smb, int bx,
                          const float* __restrict__ spanrepr) {
    const uint32_t BARS = sbase + 196608;
    int tid = threadIdx.x;
    int w = tid >> 5, lane = tid & 31;

    int row0 = (bx & 63) * 128;
    int eseg = bx >> 6;
    int ebase = eseg * (NTILES_SEG * 128);
    int tbase = eseg * NTILES_SEG;

    if (tid == 0) {
        MBAR_INIT(BARS + 0, 1);  MBAR_INIT(BARS + 8, 1);    // full (tx-based)
        MBAR_INIT(BARS + 16, 32); MBAR_INIT(BARS + 24, 32); // empty (32 warps)
    }

    // A tile: span_repr rows -> bf16 blocked SW128 layout
    for (int i = tid; i < 128 * 128; i += 1024) {
        int r = i >> 7, c = (i & 127) * 2;
        float2 v = *(const float2*)&spanrepr[(size_t)(row0 + r) * 256 + c];
        __nv_bfloat162 bb = {__float2bfloat16(v.x), __float2bfloat16(v.y)};
        STS32(sbase + tileoff(r, c * 2), *(uint32_t*)&bb);
    }
    __syncthreads();

    if (tid == 0) {
        MBAR_EXPECT_TX(BARS + 0, 65536u);
        BULK_LD(sbase + 65536, (const void*)(g_ETraw + (size_t)tbase * 65536),
                65536u, BARS + 0);
    }

    const int wr = (w >> 2) * 16;
    const int wc = (w & 3) * 32;

    uint32_t k1[8], k2[8];
#pragma unroll
    for (int j = 0; j < 8; ++j) { k1[j] = 0u; k2[j] = 0u; }

    const int a_r = wr + ((lane >> 3) & 1) * 8 + (lane & 7);
    const int a_cb = ((lane >> 4) & 1) * 16;
    const int b_rbase = wc + ((lane >> 4) & 1) * 8 + (lane & 7);
    const int b_cb = ((lane >> 3) & 1) * 16;

    const uint32_t aBase = sbase + (uint32_t)((a_r >> 3) * 1024 + (a_r & 7) * 128);
    const uint32_t aMask = (uint32_t)((a_r & 7) << 4);
    const uint32_t bBaseRel = (uint32_t)((b_rbase >> 3) * 1024 + (b_rbase & 7) * 128);
    const uint32_t bMask = (uint32_t)((b_rbase & 7) << 4);
    uint32_t aOff[4], bOff[4];
#pragma unroll
    for (int j = 0; j < 4; ++j) {
        aOff[j] = (uint32_t)((j * 32 + a_cb)) ^ aMask;
        bOff[j] = (uint32_t)((j * 32 + b_cb)) ^ bMask;
    }

#pragma unroll 1
    for (int i = 0; i < NTILES_SEG; ++i) {
        int s = i & 1, n = i >> 1;
        if (tid == 0 && i + 1 < NTILES_SEG) {
            int j = i + 1, s2 = j & 1;
            if (j >= 2) waitp(BARS + 16 + s2 * 8, ((j >> 1) + 1) & 1);
            MBAR_EXPECT_TX(BARS + 0 + s2 * 8, 65536u);
            BULK_LD(sbase + 65536 + s2 * 65536,
                    (const void*)(g_ETraw + (size_t)(tbase + j) * 65536),
                    65536u, BARS + 0 + s2 * 8);
        }
        waitp(BARS + 0 + s * 8, n & 1);

        uint32_t bBase = sbase + 65536 + s * 65536 + bBaseRel;
        float acc[4][4];
#pragma unroll
        for (int q = 0; q < 4; ++q)
#pragma unroll
            for (int j = 0; j < 4; ++j) acc[q][j] = 0.f;

#pragma unroll
        for (int ks = 0; ks < 16; ++ks) {
            const uint32_t kc = (uint32_t)((ks >> 2) * 16384);
            uint32_t a0, a1, a2, a3;
            LDMX4(a0, a1, a2, a3, aBase + kc + aOff[ks & 3]);
#pragma unroll
            for (int p = 0; p < 2; ++p) {
                uint32_t b0, b1, b2, b3;
                LDMX4(b0, b1, b2, b3, bBase + (kc + p * 2048) + bOff[ks & 3]);
                MMA16816(acc[2 * p], a0, a1, a2, a3, b0, b1);
                MMA16816(acc[2 * p + 1], a0, a1, a2, a3, b2, b3);
            }
        }
        __syncwarp();
        if (lane == 0) MBAR_ARRIVE(BARS + 16 + s * 8);  // acc in regs -> stage free

        int ebloc = i * 128 + wc + (lane & 3) * 2;
#pragma unroll
        for (int q = 0; q < 4; ++q) {
            int el = ebloc + q * 8;
            insert8u(k1, sortkey(acc[q][0], el));
            insert8u(k1, sortkey(acc[q][1], el + 1));
            insert8u(k2, sortkey(acc[q][2], el));
            insert8u(k2, sortkey(acc[q][3], el + 1));
        }
    }

    // -------- CTA merge: 16 streams/row -> top-16/row --------
    __syncthreads();
    uint32_t* mk = (uint32_t*)(smb + 65536);      // [128][128] keys (64KB)
    int sid = (w & 3) * 4 + (lane & 3);
    int r1 = wr + (lane >> 2), r2 = r1 + 8;
#pragma unroll
    for (int j = 0; j < 8; ++j) {
        mk[r1 * 128 + sid * 8 + j] = k1[j];
        mk[r2 * 128 + sid * 8 + j] = k2[j];
    }
    __syncthreads();
    if (tid < 128) {
        uint32_t tk[16];
#pragma unroll
        for (int j = 0; j < 16; ++j) tk[j] = 0u;
        for (int q = 0; q < 128; ++q) {
            uint32_t key = mk[tid * 128 + q];
            if (key > tk[15]) insert16u_slow(tk, key);
        }
        int* cp = &g_cand[((size_t)eseg * 8192 + row0 + tid) * 16];
#pragma unroll
        for (int j = 0; j < 16; ++j) {
            int e = ebase + (0x7FFF - (int)(tk[j] & 0x7FFFu));
            cp[j] = (e < NE) ? e : 0;   // clamp (padded sims never win anyway)
        }
    }
}

// ------------------------- fused topk + Y-hgemm kernel ----------------------
// blocks [0,128): topk filter; [128,520): Y = ET @ W1 (fills idle SMs).

#define FK_SMEM (1024 + 196608 + 128)

__global__ void __launch_bounds__(1024, 1)
k_fused(const float* __restrict__ spanrepr, const float* __restrict__ ET,
        const uint8_t* __restrict__ Wp1, float* __restrict__ ybuf) {
    extern __shared__ char rawsm[];
    char* smb = (char*)(((uintptr_t)rawsm + 1023) & ~(uintptr_t)1023);
    uint32_t sbase = smem_u32(smb);
    int bx = blockIdx.x;
    if (bx < 128) {
        body_topk(sbase, smb, bx, spanrepr);
    } else {
        body_hgemm<0>(sbase, bx - 128, ET, Wp1, nullptr, ybuf, NE - 1);
    }
}

// Z = h @ W2 with fused star-mix + bias epilogue -> out_sub
__global__ void __launch_bounds__(1024, 1)
k_zmix(const float* __restrict__ hbuf, const uint8_t* __restrict__ Wp2,
       const float* __restrict__ b2, float* __restrict__ out_sub) {
    extern __shared__ char rawsm[];
    char* smb = (char*)(((uintptr_t)rawsm + 1023) & ~(uintptr_t)1023);
    uint32_t sbase = smem_u32(smb);
    body_hgemm<1>(sbase, blockIdx.x, hbuf, Wp2, b2, out_sub, 65535);
}

// ------------------------- exact fp32 refine -------------------------------
__global__ void __launch_bounds__(256)
k_refine(const float* __restrict__ spanrepr, const float* __restrict__ ET) {
    int warp = threadIdx.x >> 5, lane = threadIdx.x & 31;
    int row = blockIdx.x * 8 + warp;

    __shared__ float sims[8][32];
    __shared__ int cidx[8][32];

    if (lane < 16) {
        cidx[warp][lane] = g_cand[((size_t)0 * 8192 + row) * 16 + lane];
        cidx[warp][16 + lane] = g_cand[((size_t)1 * 8192 + row) * 16 + lane];
    }
    float4 a0 = *(const float4*)&spanrepr[(size_t)row * 256 + lane * 8];
    float4 a1 = *(const float4*)&spanrepr[(size_t)row * 256 + lane * 8 + 4];
    __syncwarp();

#pragma unroll 1
    for (int c = 0; c < 32; ++c) {
        int idx = cidx[warp][c];
        const float4* ep = (const float4*)&ET[(size_t)idx * 256 + lane * 8];
        float4 e0 = ep[0], e1 = ep[1];
        float d = a0.x * e0.x + a0.y * e0.y + a0.z * e0.z + a0.w * e0.w
                + a1.x * e1.x + a1.y * e1.y + a1.z * e1.z + a1.w * e1.w;
#pragma unroll
        for (int o = 16; o; o >>= 1) d += __shfl_xor_sync(0xFFFFFFFFu, d, o);
        if (lane == 0) sims[warp][c] = d;
    }
    __syncwarp();
    if (lane == 0) {
        float tv[8]; int ti[8];
#pragma unroll
        for (int j = 0; j < 8; ++j) { tv[j] = -FLT_MAX; ti[j] = 0x7FFFFFFF; }
        for (int c = 0; c < 32; ++c) insert8(tv, ti, sims[warp][c], cidx[warp][c]);
#pragma unroll
        for (int j = 0; j < 8; ++j) g_topk[(size_t)row * 8 + j] = ti[j];
    }
}

// ------------------------- gather + mix (layer 1) ----------------------------
__global__ void k_gather_mix(const float* __restrict__ b1) {
    int n = blockIdx.x, h = threadIdx.x;
    __shared__ int id[8];
    if (h < 8) id[h] = g_topk[n * 8 + h];
    __syncthreads();
    float bb = b1[h];
    float y0 = g_ybuf[(size_t)id[0] * 256 + h];
    float s = 0.f;
    float* outb = g_hbuf + (size_t)n * 8 * 256 + h;
#pragma unroll
    for (int j = 1; j < 8; ++j) {
        float yj = g_ybuf[(size_t)id[j] * 256 + h];
        s += yj;
        outb[j * 256] = fmaxf(0.25f * y0 + 0.5f * yj + bb, 0.f);
    }
    outb[0] = fmaxf(0.125f * y0 + 0.25f * s + bb, 0.f);
}

// ------------------------- host --------------------------------------------
extern "C" void kernel_launch(void* const* d_in, const int* in_sizes, int n_in,
                              void* d_out, int out_size) {
    const float* emb = (const float*)d_in[0];
    const float* ET = (const float*)d_in[1];
    const float* spanW = (const float*)d_in[2];
    const float* spanb = (const float*)d_in[3];
    const float* W1 = (const float*)d_in[4];
    const float* b1 = (const float*)d_in[5];
    const float* W2 = (const float*)d_in[6];
    const float* b2 = (const float*)d_in[7];

    float* out = (float*)d_out;
    float* out_cls = out;                       // 4*256
    float* out_spanrepr = out + 1024;           // 8192*256
    float* out_sub = out + 1024 + 8192 * 256;   // 65536*256

    float *spanmax, *rowbias, *ybuf, *hbuf;
    uint8_t* wp;
    cudaGetSymbolAddress((void**)&spanmax, g_spanmax);
    cudaGetSymbolAddress((void**)&rowbias, g_rowbias);
    cudaGetSymbolAddress((void**)&ybuf, g_ybuf);
    cudaGetSymbolAddress((void**)&hbuf, g_hbuf);
    cudaGetSymbolAddress((void**)&wp, g_Wp);

    cudaFuncSetAttribute(gemm_span, cudaFuncAttributeMaxDynamicSharedMemorySize, SMEM_BYTES);
    cudaFuncSetAttribute(k_fused, cudaFuncAttributeMaxDynamicSharedMemorySize, FK_SMEM);
    cudaFuncSetAttribute(k_zmix, cudaFuncAttributeMaxDynamicSharedMemorySize, FK_SMEM);

    // 1) fused prep: entity bf16 pack + cls/spanmax + rowbias + W split-pack
    k_prep<<<7336, TPB>>>(emb, ET, spanW, spanb, W1, W2, out_cls);
    // 2) span_repr = spanmax @ W[0:256] + rowbias  (FFMA)
    gemm_span<<<256, TPB, SMEM_BYTES>>>(spanmax, spanW, rowbias, out_spanrepr);
    // 3) topk filter (blocks 0-127) + Y = ET@W1 on idle SMs (blocks 128-519)
    k_fused<<<128 + NEP / 128, 1024, FK_SMEM>>>(out_spanrepr, ET, wp, ybuf);
    // 4) exact fp32 refine -> sorted top-8
    k_refine<<<1024, 256>>>(out_spanrepr, ET);
    // 5) h = relu(mix(Y[topk]) + b1)
    k_gather_mix<<<NROWS, TPB>>>(b1);
    // 6) out_sub = mix(h @ W2) + b2  (fused epilogue)
    k_zmix<<<512, 1024, FK_SMEM>>>(hbuf, wp + 4 * 65536, b2, out_sub);

    (void)in_sizes; (void)n_in; (void)out_size;
}